// round 2
// baseline (speedup 1.0000x reference)
#include <cuda_runtime.h>
#include <math.h>

#define BB   4
#define TT   2048
#define DM   1024
#define NH   16
#define HD   64
#define MTOT (BB*TT)          // 8192

// ---------------- scratch (device globals: allocation-guard compliant) ------
__device__ float g_q[(size_t)BB*NH*TT*HD];   // [b,h,t,d]  33.5 MB
__device__ float g_k[(size_t)BB*NH*TT*HD];
__device__ float g_v[(size_t)BB*NH*TT*HD];
__device__ float g_ao[(size_t)MTOT*DM];      // attn output, [b,t,dm] 33.5 MB

// ===========================================================================
// SGEMM 128x128x16, 256 threads, 8x8 register tile per thread.
// As is stored transposed (As[k][m]) with row stride 132 (pad kills the
// 4-way STS bank conflict; stride stays multiple of 4 floats -> LDS.128 ok).
// ===========================================================================
#define BK   16
#define ASTR 132

__device__ __forceinline__ void gemm_core(
    const float* __restrict__ Aptr0,   // A row (m0+ar), col 0
    const float* __restrict__ Aptr1,   // A row (m0+ar+64), col 0
    const float* __restrict__ Wptr,    // W row 0, col (n0 + bc*4 [+64])
    int ldw, int ac,
    float acc[8][8], float* As, float* Bs,
    int tx, int ty)
{
#pragma unroll
    for (int i = 0; i < 8; i++)
#pragma unroll
        for (int j = 0; j < 8; j++) acc[i][j] = 0.f;

    const int ar = (threadIdx.x >> 2);         // 0..63
    const int bc4 = (threadIdx.x & 15) * 4;    // 0..60
    const int br  = (threadIdx.x >> 4);        // 0..15

    for (int k0 = 0; k0 < DM; k0 += BK) {
        float4 a0 = *(const float4*)(Aptr0 + k0);
        float4 a1 = *(const float4*)(Aptr1 + k0);
        float4 b0 = *(const float4*)(Wptr + (size_t)(k0 + br) * ldw);
        float4 b1 = *(const float4*)(Wptr + (size_t)(k0 + br) * ldw + 64);
        As[(ac*4+0)*ASTR + ar]      = a0.x;
        As[(ac*4+1)*ASTR + ar]      = a0.y;
        As[(ac*4+2)*ASTR + ar]      = a0.z;
        As[(ac*4+3)*ASTR + ar]      = a0.w;
        As[(ac*4+0)*ASTR + ar + 64] = a1.x;
        As[(ac*4+1)*ASTR + ar + 64] = a1.y;
        As[(ac*4+2)*ASTR + ar + 64] = a1.z;
        As[(ac*4+3)*ASTR + ar + 64] = a1.w;
        *(float4*)&Bs[br*128 + bc4]      = b0;
        *(float4*)&Bs[br*128 + bc4 + 64] = b1;
        __syncthreads();
#pragma unroll
        for (int kk = 0; kk < BK; kk++) {
            float a[8], b[8];
            *(float4*)&a[0] = *(float4*)&As[kk*ASTR + ty*8];
            *(float4*)&a[4] = *(float4*)&As[kk*ASTR + ty*8 + 4];
            *(float4*)&b[0] = *(float4*)&Bs[kk*128 + tx*8];
            *(float4*)&b[4] = *(float4*)&Bs[kk*128 + tx*8 + 4];
#pragma unroll
            for (int i = 0; i < 8; i++)
#pragma unroll
                for (int j = 0; j < 8; j++)
                    acc[i][j] += a[i] * b[j];
        }
        __syncthreads();
    }
}

__global__ __launch_bounds__(256) void sgemm_qkv_kernel(
    const float* __restrict__ A, const float* __restrict__ W)
{
    __shared__ float As[BK*ASTR];
    __shared__ float Bs[BK*128];

    const int tid = threadIdx.x;
    const int tx  = tid & 15, ty = tid >> 4;
    const int n0  = blockIdx.x * 128;
    const int m0  = blockIdx.y * 128;
    const int ar  = tid >> 2, ac = tid & 3;

    float acc[8][8];
    gemm_core(A + (size_t)(m0 + ar) * DM + ac * 4,
              A + (size_t)(m0 + ar + 64) * DM + ac * 4,
              W + n0 + (tid & 15) * 4,
              3*DM, ac, acc, As, Bs, tx, ty);

    // Scatter into q/k/v [b,h,t,d]. Each thread's 8 cols live in one head.
    const int col0  = n0 + tx * 8;
    const int which = col0 >> 10;            // 0=q,1=k,2=v
    const int h     = (col0 >> 6) & (NH-1);
    const int d0    = col0 & 63;
    float* Cb = (which == 0) ? g_q : ((which == 1) ? g_k : g_v);
#pragma unroll
    for (int i = 0; i < 8; i++) {
        int m = m0 + ty*8 + i;
        int b = m >> 11, t = m & (TT-1);
        float* dst = Cb + (((size_t)(b*NH + h))*TT + t)*HD + d0;
        *(float4*)(dst)     = make_float4(acc[i][0], acc[i][1], acc[i][2], acc[i][3]);
        *(float4*)(dst + 4) = make_float4(acc[i][4], acc[i][5], acc[i][6], acc[i][7]);
    }
}

__global__ __launch_bounds__(256) void sgemm_out_kernel(
    const float* __restrict__ W, float* __restrict__ Cout)
{
    __shared__ float As[BK*ASTR];
    __shared__ float Bs[BK*128];

    const int tid = threadIdx.x;
    const int tx  = tid & 15, ty = tid >> 4;
    const int n0  = blockIdx.x * 128;
    const int m0  = blockIdx.y * 128;
    const int ar  = tid >> 2, ac = tid & 3;

    float acc[8][8];
    gemm_core(g_ao + (size_t)(m0 + ar) * DM + ac * 4,
              g_ao + (size_t)(m0 + ar + 64) * DM + ac * 4,
              W + n0 + (tid & 15) * 4,
              DM, ac, acc, As, Bs, tx, ty);

#pragma unroll
    for (int i = 0; i < 8; i++) {
        int m = m0 + ty*8 + i;
        float* dst = Cout + (size_t)m * DM + n0 + tx*8;
        *(float4*)(dst)     = make_float4(acc[i][0], acc[i][1], acc[i][2], acc[i][3]);
        *(float4*)(dst + 4) = make_float4(acc[i][4], acc[i][5], acc[i][6], acc[i][7]);
    }
}

// ===========================================================================
// RoPE, in place on g_q and g_k.  One thread per (row, pair d in [0,32)).
// ===========================================================================
__global__ void rope_kernel()
{
    int gid = blockIdx.x * blockDim.x + threadIdx.x;   // < B*NH*T*32
    int d   = gid & 31;
    int row = gid >> 5;                                // (b*NH+h)*T + t
    int t   = row & (TT-1);
    size_t base = (size_t)row * HD;

    // inv_freq = 10000^(-d/32), computed in double for ulp-level agreement
    double di = exp(-(double)d * (log(10000.0) / 32.0));
    float inv = (float)di;
    float ang = (float)t * inv;
    float sn, cs;
    sincosf(ang, &sn, &cs);

    float q1 = g_q[base + d], q2 = g_q[base + d + 32];
    g_q[base + d]      = q1*cs - q2*sn;
    g_q[base + d + 32] = q2*cs + q1*sn;

    float k1 = g_k[base + d], k2 = g_k[base + d + 32];
    g_k[base + d]      = k1*cs - k2*sn;
    g_k[base + d + 32] = k2*cs + k1*sn;
}

// ===========================================================================
// Flash attention, fp32, 64x64 tiles, 256 threads, online softmax.
// Smem exactly 48 KB: Qs + (K|P overlay) + V, XOR-swizzled (&28, f4-safe).
// ===========================================================================
__global__ __launch_bounds__(256) void attn_kernel()
{
    __shared__ float Qs[4096];
    __shared__ float KPs[4096];   // K tile; reused as P tile
    __shared__ float Vs[4096];

    const int qt  = blockIdx.x;        // query tile 0..31
    const int bh  = blockIdx.y;        // 0..63
    const int tid = threadIdx.x;
    const int tx  = tid & 15, ty = tid >> 4;
    const int r0  = ty * 4;

    // load Q (pre-scaled by 1/sqrt(64))
    const float* qb = g_q + ((size_t)bh*TT + qt*64) * HD;
    for (int i4 = tid; i4 < 1024; i4 += 256) {
        int row = i4 >> 4;
        int d4  = (i4 & 15) << 2;
        float4 v = *(const float4*)(qb + row*HD + d4);
        v.x *= 0.125f; v.y *= 0.125f; v.z *= 0.125f; v.w *= 0.125f;
        *(float4*)&Qs[row*64 + (d4 ^ (row & 28))] = v;
    }

    float acc[4][4];
    float mi[4], li[4];
#pragma unroll
    for (int i = 0; i < 4; i++) {
        mi[i] = -1e30f; li[i] = 0.f;
#pragma unroll
        for (int j = 0; j < 4; j++) acc[i][j] = 0.f;
    }

    int qoff[4], qx[4];
#pragma unroll
    for (int i = 0; i < 4; i++) { int r = r0 + i; qoff[i] = r*64; qx[i] = r & 28; }
    int koff[4], kx[4];
#pragma unroll
    for (int j = 0; j < 4; j++) { int c = tx*4 + j; koff[j] = c*64; kx[j] = c & 28; }

    for (int kt = 0; kt <= qt; kt++) {
        __syncthreads();   // also covers initial Qs fill; later: P/V reads done
        const float* kb = g_k + ((size_t)bh*TT + kt*64) * HD;
        const float* vb = g_v + ((size_t)bh*TT + kt*64) * HD;
        for (int i4 = tid; i4 < 1024; i4 += 256) {
            int row = i4 >> 4;
            int d4  = (i4 & 15) << 2;
            *(float4*)&KPs[row*64 + (d4 ^ (row & 28))] = *(const float4*)(kb + row*HD + d4);
            *(float4*)&Vs [row*64 + d4]                = *(const float4*)(vb + row*HD + d4);
        }
        __syncthreads();

        // S = Q K^T  (scores, already scaled via Q)
        float s[4][4];
#pragma unroll
        for (int i = 0; i < 4; i++)
#pragma unroll
            for (int j = 0; j < 4; j++) s[i][j] = 0.f;

#pragma unroll 8
        for (int d4 = 0; d4 < 64; d4 += 4) {
            float4 qv[4], kv[4];
#pragma unroll
            for (int i = 0; i < 4; i++) qv[i] = *(float4*)&Qs[qoff[i] + (d4 ^ qx[i])];
#pragma unroll
            for (int j = 0; j < 4; j++) kv[j] = *(float4*)&KPs[koff[j] + (d4 ^ kx[j])];
#pragma unroll
            for (int i = 0; i < 4; i++)
#pragma unroll
                for (int j = 0; j < 4; j++)
                    s[i][j] += qv[i].x*kv[j].x + qv[i].y*kv[j].y
                             + qv[i].z*kv[j].z + qv[i].w*kv[j].w;
        }

        if (kt == qt) {
#pragma unroll
            for (int i = 0; i < 4; i++)
#pragma unroll
                for (int j = 0; j < 4; j++)
                    if (tx*4 + j > r0 + i) s[i][j] = -1e30f;
        }

        // online softmax (row stats replicated across the 16-lane tx group)
        float al[4];
#pragma unroll
        for (int i = 0; i < 4; i++) {
            float mx = fmaxf(fmaxf(s[i][0], s[i][1]), fmaxf(s[i][2], s[i][3]));
            for (int o = 8; o; o >>= 1) mx = fmaxf(mx, __shfl_xor_sync(0xffffffffu, mx, o));
            float mn = fmaxf(mi[i], mx);
            al[i] = __expf(mi[i] - mn);
            mi[i] = mn;
            float rs = 0.f;
#pragma unroll
            for (int j = 0; j < 4; j++) {
                float p = __expf(s[i][j] - mn);
                s[i][j] = p;
                rs += p;
            }
            for (int o = 8; o; o >>= 1) rs += __shfl_xor_sync(0xffffffffu, rs, o);
            li[i] = li[i]*al[i] + rs;
        }

        __syncthreads();   // everyone done reading KPs as K
        // write P into KPs (same &28 swizzle, float4)
#pragma unroll
        for (int i = 0; i < 4; i++)
            *(float4*)&KPs[qoff[i] + ((tx*4) ^ qx[i])] =
                make_float4(s[i][0], s[i][1], s[i][2], s[i][3]);

        // rescale accumulators
#pragma unroll
        for (int i = 0; i < 4; i++)
#pragma unroll
            for (int j = 0; j < 4; j++) acc[i][j] *= al[i];

        __syncthreads();

        // O += P @ V
#pragma unroll 8
        for (int c = 0; c < 64; c++) {
            float4 vv = *(float4*)&Vs[c*64 + tx*4];
            float p0 = KPs[qoff[0] + (c ^ qx[0])];
            float p1 = KPs[qoff[1] + (c ^ qx[1])];
            float p2 = KPs[qoff[2] + (c ^ qx[2])];
            float p3 = KPs[qoff[3] + (c ^ qx[3])];
            acc[0][0] += p0*vv.x; acc[0][1] += p0*vv.y; acc[0][2] += p0*vv.z; acc[0][3] += p0*vv.w;
            acc[1][0] += p1*vv.x; acc[1][1] += p1*vv.y; acc[1][2] += p1*vv.z; acc[1][3] += p1*vv.w;
            acc[2][0] += p2*vv.x; acc[2][1] += p2*vv.y; acc[2][2] += p2*vv.z; acc[2][3] += p2*vv.w;
            acc[3][0] += p3*vv.x; acc[3][1] += p3*vv.y; acc[3][2] += p3*vv.z; acc[3][3] += p3*vv.w;
        }
    }

    // final normalize + write to g_ao [b,t,dm]
    const int b = bh >> 4, h = bh & (NH-1);
#pragma unroll
    for (int i = 0; i < 4; i++) {
        int t = qt*64 + r0 + i;
        float inv = 1.f / li[i];
        float4 o = make_float4(acc[i][0]*inv, acc[i][1]*inv, acc[i][2]*inv, acc[i][3]*inv);
        *(float4*)(g_ao + ((size_t)b*TT + t)*DM + h*HD + tx*4) = o;
    }
}

// ===========================================================================
extern "C" void kernel_launch(void* const* d_in, const int* in_sizes, int n_in,
                              void* d_out, int out_size)
{
    const float* x    = (const float*)d_in[0];   // [4,2048,1024]
    const float* Wqkv = (const float*)d_in[1];   // [1024,3072]
    const float* Wout = (const float*)d_in[2];   // [1024,1024]
    float* out = (float*)d_out;                  // [4,2048,1024]

    sgemm_qkv_kernel<<<dim3(3*DM/128, MTOT/128), 256>>>(x, Wqkv);
    rope_kernel<<<(BB*NH*TT*32)/256, 256>>>();
    attn_kernel<<<dim3(TT/64, BB*NH), 256>>>();
    sgemm_out_kernel<<<dim3(DM/128, MTOT/128), 256>>>(Wout, out);
}

// round 3
// speedup vs baseline: 1.2012x; 1.2012x over previous
#include <cuda_runtime.h>
#include <cuda_fp16.h>
#include <mma.h>
#include <math.h>

using namespace nvcuda;

#define BB   4
#define TT   2048
#define DM   1024
#define NH   16
#define HD   64
#define MTOT (BB*TT)          // 8192

// ---------------- scratch (device globals: allocation-guard compliant) ------
__device__ float g_q[(size_t)BB*NH*TT*HD];   // [b,h,t,d]
__device__ float g_k[(size_t)BB*NH*TT*HD];
__device__ float g_v[(size_t)BB*NH*TT*HD];
__device__ float g_ao[(size_t)MTOT*DM];      // attn output, [b,t,dm]

// ===========================================================================
// Tensor-core GEMM via wmma fp16 with hi/lo split-3 (fp32-accurate):
//   a*b ~= ah*bh + ah*bl + al*bh   (dropped al*bl ~ 2^-22)
// Tile 128x128, BK=16, 256 threads = 8 warps (2 x 4), 64x32 per warp.
// ===========================================================================
#define ASTRH 24    // halfs per A-smem row (16 + 8 pad)
#define BSTRH 136   // halfs per B-smem row (128 + 8 pad)

__device__ __forceinline__ void split2(float v, __half& h, __half& l) {
    h = __float2half_rn(v);
    l = __float2half_rn(v - __half2float(h));
}

// Computes the 4x2 accumulator fragments for this warp's 64x32 sub-tile of
// C[m0:m0+128, n0:n0+128] = A[M,1024] @ W[1024, ldw-wide]
__device__ __forceinline__ void gemm_wmma_core(
    const float* __restrict__ A, const float* __restrict__ W, int ldw,
    int m0, int n0,
    wmma::fragment<wmma::accumulator,16,16,16,float> (&acc)[4][2])
{
    __shared__ __half Ah[128*ASTRH];
    __shared__ __half Al[128*ASTRH];
    __shared__ __half Bh[16*BSTRH];
    __shared__ __half Bl[16*BSTRH];

    const int tid    = threadIdx.x;
    const int wid    = tid >> 5;
    const int warp_m = wid & 1;       // 0..1  -> 64-row half
    const int warp_n = wid >> 1;      // 0..3  -> 32-col quarter

    const int arow = tid >> 1;            // 0..127
    const int akof = (tid & 1) * 8;       // 0 or 8
    const int brow = tid >> 4;            // 0..15
    const int bcol = (tid & 15) * 8;      // 0..120

#pragma unroll
    for (int i = 0; i < 4; i++)
#pragma unroll
        for (int j = 0; j < 2; j++)
            wmma::fill_fragment(acc[i][j], 0.f);

    const float* Arow = A + (size_t)(m0 + arow) * DM + akof;
    const float* Wrow = W + (size_t)brow * ldw + n0 + bcol;

    for (int k0 = 0; k0 < DM; k0 += 16) {
        // ---- fill smem (fp32 -> fp16 hi/lo) ----
        float4 a0 = *(const float4*)(Arow + k0);
        float4 a1 = *(const float4*)(Arow + k0 + 4);
        __half* ah = &Ah[arow*ASTRH + akof];
        __half* al = &Al[arow*ASTRH + akof];
        split2(a0.x, ah[0], al[0]); split2(a0.y, ah[1], al[1]);
        split2(a0.z, ah[2], al[2]); split2(a0.w, ah[3], al[3]);
        split2(a1.x, ah[4], al[4]); split2(a1.y, ah[5], al[5]);
        split2(a1.z, ah[6], al[6]); split2(a1.w, ah[7], al[7]);

        float4 b0 = *(const float4*)(Wrow + (size_t)k0 * ldw);
        float4 b1 = *(const float4*)(Wrow + (size_t)k0 * ldw + 4);
        __half* bh = &Bh[brow*BSTRH + bcol];
        __half* bl = &Bl[brow*BSTRH + bcol];
        split2(b0.x, bh[0], bl[0]); split2(b0.y, bh[1], bl[1]);
        split2(b0.z, bh[2], bl[2]); split2(b0.w, bh[3], bl[3]);
        split2(b1.x, bh[4], bl[4]); split2(b1.y, bh[5], bl[5]);
        split2(b1.z, bh[6], bl[6]); split2(b1.w, bh[7], bl[7]);
        __syncthreads();

        // ---- tensor-core work ----
        wmma::fragment<wmma::matrix_a,16,16,16,__half,wmma::row_major> fa_h[4], fa_l[4];
#pragma unroll
        for (int i = 0; i < 4; i++) {
            const int r = (warp_m*64 + i*16) * ASTRH;
            wmma::load_matrix_sync(fa_h[i], &Ah[r], ASTRH);
            wmma::load_matrix_sync(fa_l[i], &Al[r], ASTRH);
        }
#pragma unroll
        for (int j = 0; j < 2; j++) {
            wmma::fragment<wmma::matrix_b,16,16,16,__half,wmma::row_major> fb_h, fb_l;
            const int c = warp_n*32 + j*16;
            wmma::load_matrix_sync(fb_h, &Bh[c], BSTRH);
            wmma::load_matrix_sync(fb_l, &Bl[c], BSTRH);
#pragma unroll
            for (int i = 0; i < 4; i++) {
                wmma::mma_sync(acc[i][j], fa_h[i], fb_h, acc[i][j]);
                wmma::mma_sync(acc[i][j], fa_h[i], fb_l, acc[i][j]);
                wmma::mma_sync(acc[i][j], fa_l[i], fb_h, acc[i][j]);
            }
        }
        __syncthreads();
    }
}

__global__ __launch_bounds__(256) void sgemm_qkv_kernel(
    const float* __restrict__ A, const float* __restrict__ W)
{
    const int n0 = blockIdx.x * 128;
    const int m0 = blockIdx.y * 128;
    const int wid    = threadIdx.x >> 5;
    const int warp_m = wid & 1, warp_n = wid >> 1;

    wmma::fragment<wmma::accumulator,16,16,16,float> acc[4][2];
    gemm_wmma_core(A, W, 3*DM, m0, n0, acc);

    // Scatter fragments into q/k/v [b,h,t,d]; each 16-wide n-frag is inside
    // one 64-wide head block, each 16-row m-frag inside one batch.
#pragma unroll
    for (int j = 0; j < 2; j++) {
        const int col0  = n0 + warp_n*32 + j*16;
        const int which = col0 >> 10;             // 0=q,1=k,2=v
        const int h     = (col0 >> 6) & (NH-1);
        const int d0    = col0 & 63;
        float* Cb = (which == 0) ? g_q : ((which == 1) ? g_k : g_v);
#pragma unroll
        for (int i = 0; i < 4; i++) {
            const int m = m0 + warp_m*64 + i*16;
            const int b = m >> 11, t = m & (TT-1);
            float* dst = Cb + (((size_t)(b*NH + h))*TT + t)*HD + d0;
            wmma::store_matrix_sync(dst, acc[i][j], HD, wmma::mem_row_major);
        }
    }
}

__global__ __launch_bounds__(256) void sgemm_out_kernel(
    const float* __restrict__ W, float* __restrict__ Cout)
{
    const int n0 = blockIdx.x * 128;
    const int m0 = blockIdx.y * 128;
    const int wid    = threadIdx.x >> 5;
    const int warp_m = wid & 1, warp_n = wid >> 1;

    wmma::fragment<wmma::accumulator,16,16,16,float> acc[4][2];
    gemm_wmma_core(g_ao, W, DM, m0, n0, acc);

#pragma unroll
    for (int j = 0; j < 2; j++)
#pragma unroll
        for (int i = 0; i < 4; i++) {
            const int m = m0 + warp_m*64 + i*16;
            float* dst = Cout + (size_t)m * DM + n0 + warp_n*32 + j*16;
            wmma::store_matrix_sync(dst, acc[i][j], DM, wmma::mem_row_major);
        }
}

// ===========================================================================
// RoPE, in place on g_q and g_k.  One thread per (row, pair d in [0,32)).
// ===========================================================================
__global__ void rope_kernel()
{
    int gid = blockIdx.x * blockDim.x + threadIdx.x;   // < B*NH*T*32
    int d   = gid & 31;
    int row = gid >> 5;                                // (b*NH+h)*T + t
    int t   = row & (TT-1);
    size_t base = (size_t)row * HD;

    double di = exp(-(double)d * (log(10000.0) / 32.0));
    float inv = (float)di;
    float ang = (float)t * inv;
    float sn, cs;
    sincosf(ang, &sn, &cs);

    float q1 = g_q[base + d], q2 = g_q[base + d + 32];
    g_q[base + d]      = q1*cs - q2*sn;
    g_q[base + d + 32] = q2*cs + q1*sn;

    float k1 = g_k[base + d], k2 = g_k[base + d + 32];
    g_k[base + d]      = k1*cs - k2*sn;
    g_k[base + d + 32] = k2*cs + k1*sn;
}

// ===========================================================================
// Flash attention, fp32, 64x64 tiles, 256 threads, online softmax.
// Smem exactly 48 KB: Qs + (K|P overlay) + V, XOR-swizzled (&28, f4-safe).
// ===========================================================================
__global__ __launch_bounds__(256) void attn_kernel()
{
    __shared__ float Qs[4096];
    __shared__ float KPs[4096];   // K tile; reused as P tile
    __shared__ float Vs[4096];

    const int qt  = blockIdx.x;        // query tile 0..31
    const int bh  = blockIdx.y;        // 0..63
    const int tid = threadIdx.x;
    const int tx  = tid & 15, ty = tid >> 4;
    const int r0  = ty * 4;

    const float* qb = g_q + ((size_t)bh*TT + qt*64) * HD;
    for (int i4 = tid; i4 < 1024; i4 += 256) {
        int row = i4 >> 4;
        int d4  = (i4 & 15) << 2;
        float4 v = *(const float4*)(qb + row*HD + d4);
        v.x *= 0.125f; v.y *= 0.125f; v.z *= 0.125f; v.w *= 0.125f;
        *(float4*)&Qs[row*64 + (d4 ^ (row & 28))] = v;
    }

    float acc[4][4];
    float mi[4], li[4];
#pragma unroll
    for (int i = 0; i < 4; i++) {
        mi[i] = -1e30f; li[i] = 0.f;
#pragma unroll
        for (int j = 0; j < 4; j++) acc[i][j] = 0.f;
    }

    int qoff[4], qx[4];
#pragma unroll
    for (int i = 0; i < 4; i++) { int r = r0 + i; qoff[i] = r*64; qx[i] = r & 28; }
    int koff[4], kx[4];
#pragma unroll
    for (int j = 0; j < 4; j++) { int c = tx*4 + j; koff[j] = c*64; kx[j] = c & 28; }

    for (int kt = 0; kt <= qt; kt++) {
        __syncthreads();
        const float* kb = g_k + ((size_t)bh*TT + kt*64) * HD;
        const float* vb = g_v + ((size_t)bh*TT + kt*64) * HD;
        for (int i4 = tid; i4 < 1024; i4 += 256) {
            int row = i4 >> 4;
            int d4  = (i4 & 15) << 2;
            *(float4*)&KPs[row*64 + (d4 ^ (row & 28))] = *(const float4*)(kb + row*HD + d4);
            *(float4*)&Vs [row*64 + d4]                = *(const float4*)(vb + row*HD + d4);
        }
        __syncthreads();

        float s[4][4];
#pragma unroll
        for (int i = 0; i < 4; i++)
#pragma unroll
            for (int j = 0; j < 4; j++) s[i][j] = 0.f;

#pragma unroll 8
        for (int d4 = 0; d4 < 64; d4 += 4) {
            float4 qv[4], kv[4];
#pragma unroll
            for (int i = 0; i < 4; i++) qv[i] = *(float4*)&Qs[qoff[i] + (d4 ^ qx[i])];
#pragma unroll
            for (int j = 0; j < 4; j++) kv[j] = *(float4*)&KPs[koff[j] + (d4 ^ kx[j])];
#pragma unroll
            for (int i = 0; i < 4; i++)
#pragma unroll
                for (int j = 0; j < 4; j++)
                    s[i][j] += qv[i].x*kv[j].x + qv[i].y*kv[j].y
                             + qv[i].z*kv[j].z + qv[i].w*kv[j].w;
        }

        if (kt == qt) {
#pragma unroll
            for (int i = 0; i < 4; i++)
#pragma unroll
                for (int j = 0; j < 4; j++)
                    if (tx*4 + j > r0 + i) s[i][j] = -1e30f;
        }

        float al[4];
#pragma unroll
        for (int i = 0; i < 4; i++) {
            float mx = fmaxf(fmaxf(s[i][0], s[i][1]), fmaxf(s[i][2], s[i][3]));
            for (int o = 8; o; o >>= 1) mx = fmaxf(mx, __shfl_xor_sync(0xffffffffu, mx, o));
            float mn = fmaxf(mi[i], mx);
            al[i] = __expf(mi[i] - mn);
            mi[i] = mn;
            float rs = 0.f;
#pragma unroll
            for (int j = 0; j < 4; j++) {
                float p = __expf(s[i][j] - mn);
                s[i][j] = p;
                rs += p;
            }
            for (int o = 8; o; o >>= 1) rs += __shfl_xor_sync(0xffffffffu, rs, o);
            li[i] = li[i]*al[i] + rs;
        }

        __syncthreads();
#pragma unroll
        for (int i = 0; i < 4; i++)
            *(float4*)&KPs[qoff[i] + ((tx*4) ^ qx[i])] =
                make_float4(s[i][0], s[i][1], s[i][2], s[i][3]);

#pragma unroll
        for (int i = 0; i < 4; i++)
#pragma unroll
            for (int j = 0; j < 4; j++) acc[i][j] *= al[i];

        __syncthreads();

#pragma unroll 8
        for (int c = 0; c < 64; c++) {
            float4 vv = *(float4*)&Vs[c*64 + tx*4];
            float p0 = KPs[qoff[0] + (c ^ qx[0])];
            float p1 = KPs[qoff[1] + (c ^ qx[1])];
            float p2 = KPs[qoff[2] + (c ^ qx[2])];
            float p3 = KPs[qoff[3] + (c ^ qx[3])];
            acc[0][0] += p0*vv.x; acc[0][1] += p0*vv.y; acc[0][2] += p0*vv.z; acc[0][3] += p0*vv.w;
            acc[1][0] += p1*vv.x; acc[1][1] += p1*vv.y; acc[1][2] += p1*vv.z; acc[1][3] += p1*vv.w;
            acc[2][0] += p2*vv.x; acc[2][1] += p2*vv.y; acc[2][2] += p2*vv.z; acc[2][3] += p2*vv.w;
            acc[3][0] += p3*vv.x; acc[3][1] += p3*vv.y; acc[3][2] += p3*vv.z; acc[3][3] += p3*vv.w;
        }
    }

    const int b = bh >> 4, h = bh & (NH-1);
#pragma unroll
    for (int i = 0; i < 4; i++) {
        int t = qt*64 + r0 + i;
        float inv = 1.f / li[i];
        float4 o = make_float4(acc[i][0]*inv, acc[i][1]*inv, acc[i][2]*inv, acc[i][3]*inv);
        *(float4*)(g_ao + ((size_t)b*TT + t)*DM + h*HD + tx*4) = o;
    }
}

// ===========================================================================
extern "C" void kernel_launch(void* const* d_in, const int* in_sizes, int n_in,
                              void* d_out, int out_size)
{
    const float* x    = (const float*)d_in[0];   // [4,2048,1024]
    const float* Wqkv = (const float*)d_in[1];   // [1024,3072]
    const float* Wout = (const float*)d_in[2];   // [1024,1024]
    float* out = (float*)d_out;                  // [4,2048,1024]

    sgemm_qkv_kernel<<<dim3(3*DM/128, MTOT/128), 256>>>(x, Wqkv);
    rope_kernel<<<(BB*NH*TT*32)/256, 256>>>();
    attn_kernel<<<dim3(TT/64, BB*NH), 256>>>();
    sgemm_out_kernel<<<dim3(DM/128, MTOT/128), 256>>>(Wout, out);
}

// round 4
// speedup vs baseline: 2.1387x; 1.7805x over previous
#include <cuda_runtime.h>
#include <cuda_fp16.h>
#include <mma.h>
#include <math.h>

using namespace nvcuda;

#define BB   4
#define TT   2048
#define DM   1024
#define NH   16
#define HD   64
#define MTOT (BB*TT)          // 8192
#define NELEM ((size_t)MTOT*DM)   // 8388608

// ---------------- scratch (device globals: allocation-guard compliant) ------
__device__ float  g_q[NELEM], g_k[NELEM], g_v[NELEM];     // fp32 [b,h,t,d]
__device__ __half g_xh[NELEM],  g_xl[NELEM];              // x split
__device__ __half g_wqh[(size_t)DM*3*DM], g_wql[(size_t)DM*3*DM];
__device__ __half g_woh[(size_t)DM*DM],   g_wol[(size_t)DM*DM];
__device__ __half g_qh[NELEM], g_ql[NELEM];               // rope'd, pre-scaled
__device__ __half g_kh[NELEM], g_kl[NELEM];
__device__ __half g_vh[NELEM], g_vl[NELEM];
__device__ __half g_aoh[NELEM], g_aol[NELEM];             // attn out split [b,t,dm]

__device__ __forceinline__ void split2(float v, __half& h, __half& l) {
    h = __float2half_rn(v);
    l = __float2half_rn(v - __half2float(h));
}

// ===========================================================================
// fp32 -> (hi,lo) fp16 split, vectorized.  sel: 0=x, 1=Wqkv, 2=Wout
// ===========================================================================
__global__ void split_kernel(const float* __restrict__ src, int sel, int n4)
{
    __half *h, *l;
    if (sel == 0)      { h = g_xh;  l = g_xl;  }
    else if (sel == 1) { h = g_wqh; l = g_wql; }
    else               { h = g_woh; l = g_wol; }
    int i = blockIdx.x * blockDim.x + threadIdx.x;
    if (i >= n4) return;
    float4 v = ((const float4*)src)[i];
    __half hx, lx, hy, ly, hz, lz, hw, lw;
    split2(v.x, hx, lx); split2(v.y, hy, ly);
    split2(v.z, hz, lz); split2(v.w, hw, lw);
    ((__half2*)h)[2*i]   = __halves2half2(hx, hy);
    ((__half2*)h)[2*i+1] = __halves2half2(hz, hw);
    ((__half2*)l)[2*i]   = __halves2half2(lx, ly);
    ((__half2*)l)[2*i+1] = __halves2half2(lz, lw);
}

// ===========================================================================
// GEMM core: C[128x128] = A[M,1024] @ W[1024,ldw], inputs pre-split halves.
// BK=32, 256 threads = 8 warps, warp tile 64x32 (4m x 2n frags), split-3.
// ===========================================================================
#define ALD 40     // A smem row stride in halfs (32 + 8)
#define BLD 136    // B smem row stride in halfs (128 + 8)

__device__ __forceinline__ void gemm_core_h(
    const __half* __restrict__ Ah_g, const __half* __restrict__ Al_g,
    const __half* __restrict__ Bh_g, const __half* __restrict__ Bl_g,
    int ldw, int m0, int n0,
    wmma::fragment<wmma::accumulator,16,16,16,float> (&acc)[4][2])
{
    __shared__ __half Ah[128*ALD], Al[128*ALD];
    __shared__ __half Bh[32*BLD],  Bl[32*BLD];

    const int tid = threadIdx.x;
    const int wid = tid >> 5;
    const int wm  = wid & 1;      // 64-row half
    const int wn  = wid >> 1;     // 32-col quarter

#pragma unroll
    for (int i = 0; i < 4; i++)
#pragma unroll
        for (int j = 0; j < 2; j++)
            wmma::fill_fragment(acc[i][j], 0.f);

    for (int k0 = 0; k0 < DM; k0 += 32) {
#pragma unroll
        for (int u = 0; u < 2; u++) {
            int id  = tid + u*256;
            int row = id >> 2, kof = (id & 3) * 8;       // A: 128 rows x 4 units
            *(float4*)&Ah[row*ALD + kof] =
                *(const float4*)&Ah_g[(size_t)(m0+row)*DM + k0 + kof];
            *(float4*)&Al[row*ALD + kof] =
                *(const float4*)&Al_g[(size_t)(m0+row)*DM + k0 + kof];
            int brow = id >> 4, nof = (id & 15) * 8;     // B: 32 rows x 16 units
            *(float4*)&Bh[brow*BLD + nof] =
                *(const float4*)&Bh_g[(size_t)(k0+brow)*ldw + n0 + nof];
            *(float4*)&Bl[brow*BLD + nof] =
                *(const float4*)&Bl_g[(size_t)(k0+brow)*ldw + n0 + nof];
        }
        __syncthreads();
#pragma unroll
        for (int kk = 0; kk < 32; kk += 16) {
            wmma::fragment<wmma::matrix_b,16,16,16,__half,wmma::row_major> fbh[2], fbl[2];
#pragma unroll
            for (int j = 0; j < 2; j++) {
                wmma::load_matrix_sync(fbh[j], &Bh[kk*BLD + wn*32 + j*16], BLD);
                wmma::load_matrix_sync(fbl[j], &Bl[kk*BLD + wn*32 + j*16], BLD);
            }
#pragma unroll
            for (int i = 0; i < 4; i++) {
                wmma::fragment<wmma::matrix_a,16,16,16,__half,wmma::row_major> fah, fal;
                wmma::load_matrix_sync(fah, &Ah[(wm*64 + i*16)*ALD + kk], ALD);
                wmma::load_matrix_sync(fal, &Al[(wm*64 + i*16)*ALD + kk], ALD);
#pragma unroll
                for (int j = 0; j < 2; j++) {
                    wmma::mma_sync(acc[i][j], fah, fbh[j], acc[i][j]);
                    wmma::mma_sync(acc[i][j], fah, fbl[j], acc[i][j]);
                    wmma::mma_sync(acc[i][j], fal, fbh[j], acc[i][j]);
                }
            }
        }
        __syncthreads();
    }
}

__global__ __launch_bounds__(256) void qkv_gemm_kernel()
{
    const int n0 = blockIdx.x * 128, m0 = blockIdx.y * 128;
    const int wid = threadIdx.x >> 5;
    const int wm = wid & 1, wn = wid >> 1;

    wmma::fragment<wmma::accumulator,16,16,16,float> acc[4][2];
    gemm_core_h(g_xh, g_xl, g_wqh, g_wql, 3*DM, m0, n0, acc);

#pragma unroll
    for (int j = 0; j < 2; j++) {
        const int col0  = n0 + wn*32 + j*16;
        const int which = col0 >> 10;
        const int h     = (col0 >> 6) & (NH-1);
        const int d0    = col0 & 63;
        float* Cb = (which == 0) ? g_q : ((which == 1) ? g_k : g_v);
#pragma unroll
        for (int i = 0; i < 4; i++) {
            const int m = m0 + wm*64 + i*16;
            const int b = m >> 11, t = m & (TT-1);
            wmma::store_matrix_sync(Cb + (((size_t)(b*NH + h))*TT + t)*HD + d0,
                                    acc[i][j], HD, wmma::mem_row_major);
        }
    }
}

__global__ __launch_bounds__(256) void out_gemm_kernel(float* __restrict__ Cout)
{
    const int n0 = blockIdx.x * 128, m0 = blockIdx.y * 128;
    const int wid = threadIdx.x >> 5;
    const int wm = wid & 1, wn = wid >> 1;

    wmma::fragment<wmma::accumulator,16,16,16,float> acc[4][2];
    gemm_core_h(g_aoh, g_aol, g_woh, g_wol, DM, m0, n0, acc);

#pragma unroll
    for (int j = 0; j < 2; j++)
#pragma unroll
        for (int i = 0; i < 4; i++) {
            const int m = m0 + wm*64 + i*16;
            wmma::store_matrix_sync(Cout + (size_t)m*DM + n0 + wn*32 + j*16,
                                    acc[i][j], DM, wmma::mem_row_major);
        }
}

// ===========================================================================
// RoPE + hi/lo split.  q scaled by 0.125 (exact) before split.  Also splits v.
// One thread per (row, d in [0,32)).
// ===========================================================================
__global__ void rope_split_kernel()
{
    int gid = blockIdx.x * blockDim.x + threadIdx.x;
    int d   = gid & 31;
    int row = gid >> 5;
    int t   = row & (TT-1);
    size_t base = (size_t)row * HD;

    double di = exp(-(double)d * (log(10000.0) / 32.0));
    float ang = (float)t * (float)di;
    float sn, cs;
    sincosf(ang, &sn, &cs);

    float q1 = g_q[base + d], q2 = g_q[base + d + 32];
    float r1 = (q1*cs - q2*sn) * 0.125f;
    float r2 = (q2*cs + q1*sn) * 0.125f;
    split2(r1, g_qh[base+d],    g_ql[base+d]);
    split2(r2, g_qh[base+d+32], g_ql[base+d+32]);

    float k1 = g_k[base + d], k2 = g_k[base + d + 32];
    float s1 = k1*cs - k2*sn;
    float s2 = k2*cs + k1*sn;
    split2(s1, g_kh[base+d],    g_kl[base+d]);
    split2(s2, g_kh[base+d+32], g_kl[base+d+32]);

    split2(g_v[base+d],    g_vh[base+d],    g_vl[base+d]);
    split2(g_v[base+d+32], g_vh[base+d+32], g_vl[base+d+32]);
}

// ===========================================================================
// Tensor-core flash attention.  64 q-rows per block, 64-wide k tiles.
// S and PV on wmma (split-3); softmax/mask/rescale fp32 SIMT via smem.
// ===========================================================================
#define PLD 72    // half-array row stride (64 + 8)
#define SLD 68    // float-array row stride (64 + 4)

struct AttnSmem {
    __half Qh[64*PLD], Ql[64*PLD];
    __half Kh[64*PLD], Kl[64*PLD];
    __half Vh[64*PLD], Vl[64*PLD];
    __half Ph[64*PLD], Pl[64*PLD];
    float  S[64*SLD];
    float  O[64*SLD];
    float  rowm[64], rowl[64];
};

extern __shared__ char attn_smem_raw[];

__global__ __launch_bounds__(256) void attn_kernel()
{
    AttnSmem& sm = *(AttnSmem*)attn_smem_raw;
    const int qt  = blockIdx.x;      // 0..31
    const int bh  = blockIdx.y;      // 0..63
    const int tid = threadIdx.x;
    const int wid = tid >> 5;
    const int mq  = wid >> 2;        // 0..1 : owns m-frags {2mq, 2mq+1}
    const int wn  = wid & 3;         // 0..3 : n-frag column

    // ---- load Q tile (pre-scaled halves) ----
    const size_t qbase = ((size_t)bh*TT + qt*64) * HD;
#pragma unroll
    for (int u = 0; u < 2; u++) {
        int id = tid + u*256;
        int row = id >> 3, kof = (id & 7) * 8;
        *(float4*)&sm.Qh[row*PLD + kof] = *(const float4*)&g_qh[qbase + row*HD + kof];
        *(float4*)&sm.Ql[row*PLD + kof] = *(const float4*)&g_ql[qbase + row*HD + kof];
    }
    for (int i = tid; i < 64*SLD; i += 256) sm.O[i] = 0.f;
    if (tid < 64) { sm.rowm[tid] = -1e30f; sm.rowl[tid] = 0.f; }

    for (int kt = 0; kt <= qt; kt++) {
        __syncthreads();   // covers init / prior PV reads of K,V
        const size_t kbase = ((size_t)bh*TT + kt*64) * HD;
#pragma unroll
        for (int u = 0; u < 2; u++) {
            int id = tid + u*256;
            int row = id >> 3, kof = (id & 7) * 8;
            *(float4*)&sm.Kh[row*PLD + kof] = *(const float4*)&g_kh[kbase + row*HD + kof];
            *(float4*)&sm.Kl[row*PLD + kof] = *(const float4*)&g_kl[kbase + row*HD + kof];
            *(float4*)&sm.Vh[row*PLD + kof] = *(const float4*)&g_vh[kbase + row*HD + kof];
            *(float4*)&sm.Vl[row*PLD + kof] = *(const float4*)&g_vl[kbase + row*HD + kof];
        }
        __syncthreads();

        // ---- S = Q K^T (split-3) ----
        {
            wmma::fragment<wmma::accumulator,16,16,16,float> s0, s1;
            wmma::fill_fragment(s0, 0.f);
            wmma::fill_fragment(s1, 0.f);
#pragma unroll
            for (int k = 0; k < 4; k++) {
                wmma::fragment<wmma::matrix_b,16,16,16,__half,wmma::col_major> fbh, fbl;
                wmma::load_matrix_sync(fbh, &sm.Kh[(wn*16)*PLD + k*16], PLD);
                wmma::load_matrix_sync(fbl, &sm.Kl[(wn*16)*PLD + k*16], PLD);
#pragma unroll
                for (int i = 0; i < 2; i++) {
                    wmma::fragment<wmma::matrix_a,16,16,16,__half,wmma::row_major> fah, fal;
                    wmma::load_matrix_sync(fah, &sm.Qh[((2*mq+i)*16)*PLD + k*16], PLD);
                    wmma::load_matrix_sync(fal, &sm.Ql[((2*mq+i)*16)*PLD + k*16], PLD);
                    wmma::fragment<wmma::accumulator,16,16,16,float>& a = i ? s1 : s0;
                    wmma::mma_sync(a, fah, fbh, a);
                    wmma::mma_sync(a, fah, fbl, a);
                    wmma::mma_sync(a, fal, fbh, a);
                }
            }
            wmma::store_matrix_sync(&sm.S[((2*mq  )*16)*SLD + wn*16], s0, SLD, wmma::mem_row_major);
            wmma::store_matrix_sync(&sm.S[((2*mq+1)*16)*SLD + wn*16], s1, SLD, wmma::mem_row_major);
        }
        __syncthreads();

        // ---- softmax (fp32 SIMT; 4 lanes per row) ----
        {
            const int r  = tid >> 2;
            const int c0 = (tid & 3) * 16;
            const bool diag = (kt == qt);
            float sv[16];
            float mx = -1e30f;
#pragma unroll
            for (int c = 0; c < 16; c++) {
                float s = sm.S[r*SLD + c0 + c];
                if (diag && (c0 + c) > r) s = -1e30f;
                sv[c] = s;
                mx = fmaxf(mx, s);
            }
            mx = fmaxf(mx, __shfl_xor_sync(0xffffffffu, mx, 1));
            mx = fmaxf(mx, __shfl_xor_sync(0xffffffffu, mx, 2));
            float mold  = sm.rowm[r];
            float mn    = fmaxf(mold, mx);
            float alpha = __expf(mold - mn);
            float sum = 0.f;
#pragma unroll
            for (int c = 0; c < 16; c++) {
                float p = __expf(sv[c] - mn);
                sum += p;
                split2(p, sm.Ph[r*PLD + c0 + c], sm.Pl[r*PLD + c0 + c]);
            }
            sum += __shfl_xor_sync(0xffffffffu, sum, 1);
            sum += __shfl_xor_sync(0xffffffffu, sum, 2);
            if ((tid & 3) == 0) {
                sm.rowm[r] = mn;
                sm.rowl[r] = sm.rowl[r]*alpha + sum;
            }
#pragma unroll
            for (int c = 0; c < 16; c++) sm.O[r*SLD + c0 + c] *= alpha;
        }
        __syncthreads();

        // ---- O += P V (split-3) ----
        {
            wmma::fragment<wmma::accumulator,16,16,16,float> o0, o1;
            wmma::load_matrix_sync(o0, &sm.O[((2*mq  )*16)*SLD + wn*16], SLD, wmma::mem_row_major);
            wmma::load_matrix_sync(o1, &sm.O[((2*mq+1)*16)*SLD + wn*16], SLD, wmma::mem_row_major);
#pragma unroll
            for (int k = 0; k < 4; k++) {
                wmma::fragment<wmma::matrix_b,16,16,16,__half,wmma::row_major> fbh, fbl;
                wmma::load_matrix_sync(fbh, &sm.Vh[(k*16)*PLD + wn*16], PLD);
                wmma::load_matrix_sync(fbl, &sm.Vl[(k*16)*PLD + wn*16], PLD);
#pragma unroll
                for (int i = 0; i < 2; i++) {
                    wmma::fragment<wmma::matrix_a,16,16,16,__half,wmma::row_major> fah, fal;
                    wmma::load_matrix_sync(fah, &sm.Ph[((2*mq+i)*16)*PLD + k*16], PLD);
                    wmma::load_matrix_sync(fal, &sm.Pl[((2*mq+i)*16)*PLD + k*16], PLD);
                    wmma::fragment<wmma::accumulator,16,16,16,float>& a = i ? o1 : o0;
                    wmma::mma_sync(a, fah, fbh, a);
                    wmma::mma_sync(a, fah, fbl, a);
                    wmma::mma_sync(a, fal, fbh, a);
                }
            }
            wmma::store_matrix_sync(&sm.O[((2*mq  )*16)*SLD + wn*16], o0, SLD, wmma::mem_row_major);
            wmma::store_matrix_sync(&sm.O[((2*mq+1)*16)*SLD + wn*16], o1, SLD, wmma::mem_row_major);
        }
    }
    __syncthreads();

    // ---- epilogue: normalize, split, write [b,t,dm] halves ----
    {
        const int r  = tid >> 2;
        const int c0 = (tid & 3) * 16;
        const float inv = 1.f / sm.rowl[r];
        const int b = bh >> 4, h = bh & (NH-1);
        const size_t obase = (((size_t)b*TT) + qt*64 + r)*DM + h*HD;
#pragma unroll
        for (int c = 0; c < 16; c++) {
            float o = sm.O[r*SLD + c0 + c] * inv;
            split2(o, g_aoh[obase + c0 + c], g_aol[obase + c0 + c]);
        }
    }
}

// ===========================================================================
extern "C" void kernel_launch(void* const* d_in, const int* in_sizes, int n_in,
                              void* d_out, int out_size)
{
    const float* x    = (const float*)d_in[0];   // [4,2048,1024]
    const float* Wqkv = (const float*)d_in[1];   // [1024,3072]
    const float* Wout = (const float*)d_in[2];   // [1024,1024]
    float* out = (float*)d_out;                  // [4,2048,1024]

    cudaFuncSetAttribute(attn_kernel, cudaFuncAttributeMaxDynamicSharedMemorySize,
                         (int)sizeof(AttnSmem));

    split_kernel<<<(NELEM/4 + 255)/256, 256>>>(x, 0, (int)(NELEM/4));
    split_kernel<<<(DM*3*DM/4 + 255)/256, 256>>>(Wqkv, 1, DM*3*DM/4);
    split_kernel<<<(DM*DM/4 + 255)/256, 256>>>(Wout, 2, DM*DM/4);

    qkv_gemm_kernel<<<dim3(3*DM/128, MTOT/128), 256>>>();
    rope_split_kernel<<<(BB*NH*TT*32)/256, 256>>>();
    attn_kernel<<<dim3(TT/64, BB*NH), 256, sizeof(AttnSmem)>>>();
    out_gemm_kernel<<<dim3(DM/128, MTOT/128), 256>>>(out);
}

// round 6
// speedup vs baseline: 2.6185x; 1.2243x over previous
#include <cuda_runtime.h>
#include <cuda_fp16.h>
#include <mma.h>
#include <math.h>
#include <stdint.h>

using namespace nvcuda;

#define BB   4
#define TT   2048
#define DM   1024
#define NH   16
#define HD   64
#define MTOT (BB*TT)              // 8192
#define NELEM ((size_t)MTOT*DM)   // 8388608

// ---------------- scratch (device globals: allocation-guard compliant) ------
__device__ float  g_q[NELEM], g_k[NELEM], g_v[NELEM];     // fp32 [b,h,t,d]
__device__ __half g_xh[NELEM],  g_xl[NELEM];
__device__ __half g_wqh[(size_t)DM*3*DM], g_wql[(size_t)DM*3*DM];
__device__ __half g_woh[(size_t)DM*DM],   g_wol[(size_t)DM*DM];
__device__ __half g_qh[NELEM], g_ql[NELEM];               // rope'd, pre-scaled
__device__ __half g_kh[NELEM], g_kl[NELEM];
__device__ __half g_vh[NELEM], g_vl[NELEM];
__device__ __half g_aoh[NELEM], g_aol[NELEM];             // attn out split [b,t,dm]

__device__ __forceinline__ void split2(float v, __half& h, __half& l) {
    h = __float2half_rn(v);
    l = __float2half_rn(v - __half2float(h));
}

// ---------------- async-copy / ldmatrix / mma primitives --------------------
__device__ __forceinline__ void cp16(void* dst, const void* src) {
    uint32_t d = (uint32_t)__cvta_generic_to_shared(dst);
    asm volatile("cp.async.cg.shared.global [%0], [%1], 16;\n" :: "r"(d), "l"(src));
}
__device__ __forceinline__ void cp_commit() {
    asm volatile("cp.async.commit_group;\n");
}
template<int N> __device__ __forceinline__ void cp_wait() {
    asm volatile("cp.async.wait_group %0;\n" :: "n"(N));
}
__device__ __forceinline__ void ldsm4(uint32_t* r, const __half* p) {
    uint32_t a = (uint32_t)__cvta_generic_to_shared(p);
    asm volatile("ldmatrix.sync.aligned.m8n8.x4.shared.b16 {%0,%1,%2,%3}, [%4];\n"
        : "=r"(r[0]), "=r"(r[1]), "=r"(r[2]), "=r"(r[3]) : "r"(a));
}
__device__ __forceinline__ void ldsm4t(uint32_t* r, const __half* p) {
    uint32_t a = (uint32_t)__cvta_generic_to_shared(p);
    asm volatile("ldmatrix.sync.aligned.m8n8.x4.trans.shared.b16 {%0,%1,%2,%3}, [%4];\n"
        : "=r"(r[0]), "=r"(r[1]), "=r"(r[2]), "=r"(r[3]) : "r"(a));
}
__device__ __forceinline__ void mma16816(float* c, const uint32_t* a,
                                         uint32_t b0, uint32_t b1) {
    asm volatile("mma.sync.aligned.m16n8k16.row.col.f32.f16.f16.f32 "
        "{%0,%1,%2,%3}, {%4,%5,%6,%7}, {%8,%9}, {%0,%1,%2,%3};\n"
        : "+f"(c[0]), "+f"(c[1]), "+f"(c[2]), "+f"(c[3])
        : "r"(a[0]), "r"(a[1]), "r"(a[2]), "r"(a[3]), "r"(b0), "r"(b1));
}
__device__ __forceinline__ void split_h2(float x, float y, uint32_t& hi, uint32_t& lo) {
    __half hx = __float2half_rn(x), hy = __float2half_rn(y);
    __half lx = __float2half_rn(x - __half2float(hx));
    __half ly = __float2half_rn(y - __half2float(hy));
    __half2 H = __halves2half2(hx, hy), L = __halves2half2(lx, ly);
    hi = *(uint32_t*)&H; lo = *(uint32_t*)&L;
}

extern __shared__ __half gsm[];

// ===========================================================================
// fp32 -> (hi,lo) fp16 split.  sel: 0=x, 1=Wqkv, 2=Wout
// ===========================================================================
__global__ void split_kernel(const float* __restrict__ src, int sel, int n4)
{
    __half *h, *l;
    if (sel == 0)      { h = g_xh;  l = g_xl;  }
    else if (sel == 1) { h = g_wqh; l = g_wql; }
    else               { h = g_woh; l = g_wol; }
    int i = blockIdx.x * blockDim.x + threadIdx.x;
    if (i >= n4) return;
    float4 v = ((const float4*)src)[i];
    __half hx, lx, hy, ly, hz, lz, hw, lw;
    split2(v.x, hx, lx); split2(v.y, hy, ly);
    split2(v.z, hz, lz); split2(v.w, hw, lw);
    ((__half2*)h)[2*i]   = __halves2half2(hx, hy);
    ((__half2*)h)[2*i+1] = __halves2half2(hz, hw);
    ((__half2*)l)[2*i]   = __halves2half2(lx, ly);
    ((__half2*)l)[2*i+1] = __halves2half2(lz, lw);
}

// ===========================================================================
// GEMM 128x128, BK=32, 8 warps (warp tile 64x32), split-3, cp.async double buf
// ===========================================================================
#define ALD 40
#define BLD 136
#define AHS (128*ALD)
#define BHS (32*BLD)
#define GEMM_SMEM ((2*(2*AHS + 2*BHS))*2)   // bytes = 75776

__device__ __forceinline__ void gemm_issue(
    const __half* __restrict__ Ah_g, const __half* __restrict__ Al_g,
    const __half* __restrict__ Bh_g, const __half* __restrict__ Bl_g,
    int ldw, int m0, int n0, int k0, int buf)
{
    __half* base = gsm + buf*(2*AHS + 2*BHS);
    __half* Ah = base;            __half* Al = base + AHS;
    __half* Bh = base + 2*AHS;    __half* Bl = base + 2*AHS + BHS;
    const int tid = threadIdx.x;
#pragma unroll
    for (int u = 0; u < 2; u++) {
        int id = tid + u*256;
        int ar = id >> 2, ak = (id & 3)*8;
        cp16(&Ah[ar*ALD + ak], &Ah_g[(size_t)(m0+ar)*DM + k0 + ak]);
        cp16(&Al[ar*ALD + ak], &Al_g[(size_t)(m0+ar)*DM + k0 + ak]);
        int br = id >> 4, bn = (id & 15)*8;
        cp16(&Bh[br*BLD + bn], &Bh_g[(size_t)(k0+br)*ldw + n0 + bn]);
        cp16(&Bl[br*BLD + bn], &Bl_g[(size_t)(k0+br)*ldw + n0 + bn]);
    }
    cp_commit();
}

__device__ __forceinline__ void gemm_compute(
    int buf, int wm, int wn,
    wmma::fragment<wmma::accumulator,16,16,16,float> (&acc)[4][2])
{
    __half* base = gsm + buf*(2*AHS + 2*BHS);
    __half* Ah = base;            __half* Al = base + AHS;
    __half* Bh = base + 2*AHS;    __half* Bl = base + 2*AHS + BHS;
#pragma unroll
    for (int kk = 0; kk < 32; kk += 16) {
        wmma::fragment<wmma::matrix_b,16,16,16,__half,wmma::row_major> fbh[2], fbl[2];
#pragma unroll
        for (int j = 0; j < 2; j++) {
            wmma::load_matrix_sync(fbh[j], &Bh[kk*BLD + wn*32 + j*16], BLD);
            wmma::load_matrix_sync(fbl[j], &Bl[kk*BLD + wn*32 + j*16], BLD);
        }
#pragma unroll
        for (int i = 0; i < 4; i++) {
            wmma::fragment<wmma::matrix_a,16,16,16,__half,wmma::row_major> fah, fal;
            wmma::load_matrix_sync(fah, &Ah[(wm*64 + i*16)*ALD + kk], ALD);
            wmma::load_matrix_sync(fal, &Al[(wm*64 + i*16)*ALD + kk], ALD);
#pragma unroll
            for (int j = 0; j < 2; j++) {
                wmma::mma_sync(acc[i][j], fah, fbh[j], acc[i][j]);
                wmma::mma_sync(acc[i][j], fah, fbl[j], acc[i][j]);
                wmma::mma_sync(acc[i][j], fal, fbh[j], acc[i][j]);
            }
        }
    }
}

__device__ __forceinline__ void gemm_core_db(
    const __half* Ah_g, const __half* Al_g,
    const __half* Bh_g, const __half* Bl_g,
    int ldw, int m0, int n0,
    wmma::fragment<wmma::accumulator,16,16,16,float> (&acc)[4][2])
{
#pragma unroll
    for (int i = 0; i < 4; i++)
#pragma unroll
        for (int j = 0; j < 2; j++)
            wmma::fill_fragment(acc[i][j], 0.f);

    gemm_issue(Ah_g, Al_g, Bh_g, Bl_g, ldw, m0, n0, 0, 0);
    int buf = 0;
    for (int k0 = 0; k0 < DM; k0 += 32, buf ^= 1) {
        if (k0 + 32 < DM) {
            gemm_issue(Ah_g, Al_g, Bh_g, Bl_g, ldw, m0, n0, k0 + 32, buf ^ 1);
            cp_wait<1>();
        } else {
            cp_wait<0>();
        }
        __syncthreads();
        gemm_compute(buf, (threadIdx.x >> 5) & 1, threadIdx.x >> 6, acc);
        __syncthreads();
    }
}

__global__ __launch_bounds__(256) void qkv_gemm_kernel()
{
    const int n0 = blockIdx.x * 128, m0 = blockIdx.y * 128;
    const int wid = threadIdx.x >> 5;
    const int wm = wid & 1, wn = wid >> 1;

    wmma::fragment<wmma::accumulator,16,16,16,float> acc[4][2];
    gemm_core_db(g_xh, g_xl, g_wqh, g_wql, 3*DM, m0, n0, acc);

#pragma unroll
    for (int j = 0; j < 2; j++) {
        const int col0  = n0 + wn*32 + j*16;
        const int which = col0 >> 10;
        const int h     = (col0 >> 6) & (NH-1);
        const int d0    = col0 & 63;
        float* Cb = (which == 0) ? g_q : ((which == 1) ? g_k : g_v);
#pragma unroll
        for (int i = 0; i < 4; i++) {
            const int m = m0 + wm*64 + i*16;
            const int b = m >> 11, t = m & (TT-1);
            wmma::store_matrix_sync(Cb + (((size_t)(b*NH + h))*TT + t)*HD + d0,
                                    acc[i][j], HD, wmma::mem_row_major);
        }
    }
}

__global__ __launch_bounds__(256) void out_gemm_kernel(float* __restrict__ Cout)
{
    const int n0 = blockIdx.x * 128, m0 = blockIdx.y * 128;
    const int wid = threadIdx.x >> 5;
    const int wm = wid & 1, wn = wid >> 1;

    wmma::fragment<wmma::accumulator,16,16,16,float> acc[4][2];
    gemm_core_db(g_aoh, g_aol, g_woh, g_wol, DM, m0, n0, acc);

#pragma unroll
    for (int j = 0; j < 2; j++)
#pragma unroll
        for (int i = 0; i < 4; i++) {
            const int m = m0 + wm*64 + i*16;
            wmma::store_matrix_sync(Cout + (size_t)m*DM + n0 + wn*32 + j*16,
                                    acc[i][j], DM, wmma::mem_row_major);
        }
}

// ===========================================================================
// RoPE + hi/lo split.  q scaled by 0.125 (exact) before split.  Also splits v.
// ===========================================================================
__global__ void rope_split_kernel()
{
    int gid = blockIdx.x * blockDim.x + threadIdx.x;
    int d   = gid & 31;
    int row = gid >> 5;
    int t   = row & (TT-1);
    size_t base = (size_t)row * HD;

    double di = exp(-(double)d * (log(10000.0) / 32.0));
    float ang = (float)t * (float)di;
    float sn, cs;
    sincosf(ang, &sn, &cs);

    float q1 = g_q[base + d], q2 = g_q[base + d + 32];
    float r1 = (q1*cs - q2*sn) * 0.125f;
    float r2 = (q2*cs + q1*sn) * 0.125f;
    split2(r1, g_qh[base+d],    g_ql[base+d]);
    split2(r2, g_qh[base+d+32], g_ql[base+d+32]);

    float k1 = g_k[base + d], k2 = g_k[base + d + 32];
    float s1 = k1*cs - k2*sn;
    float s2 = k2*cs + k1*sn;
    split2(s1, g_kh[base+d],    g_kl[base+d]);
    split2(s2, g_kh[base+d+32], g_kl[base+d+32]);

    split2(g_v[base+d],    g_vh[base+d],    g_vl[base+d]);
    split2(g_v[base+d+32], g_vh[base+d+32], g_vl[base+d+32]);
}

// ===========================================================================
// FA2-style flash attention on raw mma.sync.m16n8k16, split-3.
// 128 q-rows/block, 8 warps (16 rows each), 64-key tiles, softmax in regs.
// K/V and Q staged via cp.async.
// ===========================================================================
#define PLD  72
#define AQ_S (128*PLD)
#define KV_S (64*PLD)
#define ATTN_SMEM ((2*AQ_S + 4*KV_S)*2)   // 73728 bytes

__global__ __launch_bounds__(256) void attn_kernel()
{
    __half* Qh = gsm;
    __half* Ql = gsm + AQ_S;
    __half* Kh = gsm + 2*AQ_S;
    __half* Kl = Kh + KV_S;
    __half* Vh = Kl + KV_S;
    __half* Vl = Vh + KV_S;

    const int qt   = blockIdx.x;       // 0..15 (128-row q tiles)
    const int bh   = blockIdx.y;       // 0..63
    const int tid  = threadIdx.x;
    const int lane = tid & 31;
    const int w    = tid >> 5;         // 0..7, warp owns rows w*16..+15
    const int lr   = lane & 15;        // ldmatrix row (Q / V pattern)
    const int lc8  = (lane >> 4) << 3; // ldmatrix col offset (Q / V pattern)
    const int krow = ((lane >> 4) << 3) | (lane & 7);   // K pattern row
    const int kc8  = ((lane >> 3) & 1) << 3;            // K pattern col offset

    // ---- stage Q tile via cp.async, load Q fragments into registers ----
    const size_t qbase = ((size_t)bh*TT + qt*128) * HD;
#pragma unroll
    for (int u = 0; u < 4; u++) {
        int id = tid + u*256;
        int row = id >> 3, kof = (id & 7)*8;
        cp16(&Qh[row*PLD + kof], &g_qh[qbase + (size_t)row*HD + kof]);
        cp16(&Ql[row*PLD + kof], &g_ql[qbase + (size_t)row*HD + kof]);
    }
    cp_commit();
    cp_wait<0>();
    __syncthreads();

    uint32_t qfh[4][4], qfl[4][4];
#pragma unroll
    for (int kk = 0; kk < 4; kk++) {
        ldsm4(qfh[kk], &Qh[(w*16 + lr)*PLD + kk*16 + lc8]);
        ldsm4(qfl[kk], &Ql[(w*16 + lr)*PLD + kk*16 + lc8]);
    }

    float o[8][4];
#pragma unroll
    for (int j = 0; j < 8; j++)
#pragma unroll
        for (int i = 0; i < 4; i++) o[j][i] = 0.f;
    float m0r = -1e30f, m1r = -1e30f, l0r = 0.f, l1r = 0.f;

    const int grow0 = qt*128 + w*16 + (lane >> 2);   // this thread's row (g)
    const int ktmax = 2*qt + 1;

    for (int kt = 0; kt <= ktmax; kt++) {
        __syncthreads();                     // prior iter done reading K/V
        const size_t kvb = ((size_t)bh*TT + kt*64) * HD;
#pragma unroll
        for (int u = 0; u < 2; u++) {
            int id = tid + u*256;
            int row = id >> 3, kof = (id & 7)*8;
            size_t src = kvb + (size_t)row*HD + kof;
            cp16(&Kh[row*PLD + kof], &g_kh[src]);
            cp16(&Kl[row*PLD + kof], &g_kl[src]);
            cp16(&Vh[row*PLD + kof], &g_vh[src]);
            cp16(&Vl[row*PLD + kof], &g_vl[src]);
        }
        cp_commit();
        cp_wait<0>();
        __syncthreads();

        if (kt*64 > qt*128 + w*16 + 15) continue;   // warp fully masked

        // ---- S = Q K^T (8 n8-frags per warp, split-3) ----
        float sc[8][4];
#pragma unroll
        for (int j = 0; j < 8; j++)
#pragma unroll
            for (int i = 0; i < 4; i++) sc[j][i] = 0.f;

#pragma unroll
        for (int kk = 0; kk < 4; kk++) {
#pragma unroll
            for (int jj = 0; jj < 4; jj++) {
                uint32_t kbh[4], kbl[4];
                const int koff = (jj*16 + krow)*PLD + kk*16 + kc8;
                ldsm4(kbh, &Kh[koff]);
                ldsm4(kbl, &Kl[koff]);
                mma16816(sc[2*jj],   qfh[kk], kbh[0], kbh[1]);
                mma16816(sc[2*jj],   qfh[kk], kbl[0], kbl[1]);
                mma16816(sc[2*jj],   qfl[kk], kbh[0], kbh[1]);
                mma16816(sc[2*jj+1], qfh[kk], kbh[2], kbh[3]);
                mma16816(sc[2*jj+1], qfh[kk], kbl[2], kbl[3]);
                mma16816(sc[2*jj+1], qfl[kk], kbh[2], kbh[3]);
            }
        }

        // ---- causal mask ----
        if (kt*64 + 63 > qt*128 + w*16) {
            const int cb = kt*64 + (lane & 3)*2;
#pragma unroll
            for (int j = 0; j < 8; j++) {
                int c0 = cb + j*8;
                if (c0     > grow0)     sc[j][0] = -1e30f;
                if (c0 + 1 > grow0)     sc[j][1] = -1e30f;
                if (c0     > grow0 + 8) sc[j][2] = -1e30f;
                if (c0 + 1 > grow0 + 8) sc[j][3] = -1e30f;
            }
        }

        // ---- online softmax in registers ----
        float mx0 = -1e30f, mx1 = -1e30f;
#pragma unroll
        for (int j = 0; j < 8; j++) {
            mx0 = fmaxf(mx0, fmaxf(sc[j][0], sc[j][1]));
            mx1 = fmaxf(mx1, fmaxf(sc[j][2], sc[j][3]));
        }
        mx0 = fmaxf(mx0, __shfl_xor_sync(0xffffffffu, mx0, 1));
        mx0 = fmaxf(mx0, __shfl_xor_sync(0xffffffffu, mx0, 2));
        mx1 = fmaxf(mx1, __shfl_xor_sync(0xffffffffu, mx1, 1));
        mx1 = fmaxf(mx1, __shfl_xor_sync(0xffffffffu, mx1, 2));

        float mn0 = fmaxf(m0r, mx0), mn1 = fmaxf(m1r, mx1);
        float al0 = __expf(m0r - mn0), al1 = __expf(m1r - mn1);
        m0r = mn0; m1r = mn1;

        float s0 = 0.f, s1 = 0.f;
#pragma unroll
        for (int j = 0; j < 8; j++) {
            sc[j][0] = __expf(sc[j][0] - mn0);  s0 += sc[j][0];
            sc[j][1] = __expf(sc[j][1] - mn0);  s0 += sc[j][1];
            sc[j][2] = __expf(sc[j][2] - mn1);  s1 += sc[j][2];
            sc[j][3] = __expf(sc[j][3] - mn1);  s1 += sc[j][3];
        }
        s0 += __shfl_xor_sync(0xffffffffu, s0, 1);
        s0 += __shfl_xor_sync(0xffffffffu, s0, 2);
        s1 += __shfl_xor_sync(0xffffffffu, s1, 1);
        s1 += __shfl_xor_sync(0xffffffffu, s1, 2);
        l0r = l0r*al0 + s0;
        l1r = l1r*al1 + s1;

#pragma unroll
        for (int j = 0; j < 8; j++) {
            o[j][0] *= al0; o[j][1] *= al0;
            o[j][2] *= al1; o[j][3] *= al1;
        }

        // ---- O += P V (P frags built in registers, split-3) ----
#pragma unroll
        for (int cc = 0; cc < 4; cc++) {
            uint32_t pah[4], pal[4];
            split_h2(sc[2*cc][0],   sc[2*cc][1],   pah[0], pal[0]);
            split_h2(sc[2*cc][2],   sc[2*cc][3],   pah[1], pal[1]);
            split_h2(sc[2*cc+1][0], sc[2*cc+1][1], pah[2], pal[2]);
            split_h2(sc[2*cc+1][2], sc[2*cc+1][3], pah[3], pal[3]);
#pragma unroll
            for (int jj = 0; jj < 4; jj++) {
                uint32_t vbh[4], vbl[4];
                const int voff = (cc*16 + lr)*PLD + jj*16 + lc8;
                ldsm4t(vbh, &Vh[voff]);
                ldsm4t(vbl, &Vl[voff]);
                mma16816(o[2*jj],   pah, vbh[0], vbh[1]);
                mma16816(o[2*jj],   pah, vbl[0], vbl[1]);
                mma16816(o[2*jj],   pal, vbh[0], vbh[1]);
                mma16816(o[2*jj+1], pah, vbh[2], vbh[3]);
                mma16816(o[2*jj+1], pah, vbl[2], vbl[3]);
                mma16816(o[2*jj+1], pal, vbh[2], vbh[3]);
            }
        }
    }

    // ---- epilogue: normalize, split, write [b,t,dm] halves ----
    const float inv0 = 1.f / l0r, inv1 = 1.f / l1r;
    const int b = bh >> 4, h = bh & (NH-1);
    const size_t ob0 = ((size_t)b*TT + grow0)*DM + h*HD;
    const size_t ob1 = ob0 + (size_t)8*DM;
#pragma unroll
    for (int j = 0; j < 8; j++) {
        int col = j*8 + (lane & 3)*2;
        split2(o[j][0]*inv0, g_aoh[ob0+col],   g_aol[ob0+col]);
        split2(o[j][1]*inv0, g_aoh[ob0+col+1], g_aol[ob0+col+1]);
        split2(o[j][2]*inv1, g_aoh[ob1+col],   g_aol[ob1+col]);
        split2(o[j][3]*inv1, g_aoh[ob1+col+1], g_aol[ob1+col+1]);
    }
}

// ===========================================================================
extern "C" void kernel_launch(void* const* d_in, const int* in_sizes, int n_in,
                              void* d_out, int out_size)
{
    const float* x    = (const float*)d_in[0];   // [4,2048,1024]
    const float* Wqkv = (const float*)d_in[1];   // [1024,3072]
    const float* Wout = (const float*)d_in[2];   // [1024,1024]
    float* out = (float*)d_out;                  // [4,2048,1024]

    cudaFuncSetAttribute(qkv_gemm_kernel, cudaFuncAttributeMaxDynamicSharedMemorySize, GEMM_SMEM);
    cudaFuncSetAttribute(out_gemm_kernel, cudaFuncAttributeMaxDynamicSharedMemorySize, GEMM_SMEM);
    cudaFuncSetAttribute(attn_kernel,     cudaFuncAttributeMaxDynamicSharedMemorySize, ATTN_SMEM);

    split_kernel<<<(NELEM/4 + 255)/256, 256>>>(x, 0, (int)(NELEM/4));
    split_kernel<<<(DM*3*DM/4 + 255)/256, 256>>>(Wqkv, 1, DM*3*DM/4);
    split_kernel<<<(DM*DM/4 + 255)/256, 256>>>(Wout, 2, DM*DM/4);

    qkv_gemm_kernel<<<dim3(3*DM/128, MTOT/128), 256, GEMM_SMEM>>>();
    rope_split_kernel<<<(BB*NH*TT*32)/256, 256>>>();
    attn_kernel<<<dim3(TT/128, BB*NH), 256, ATTN_SMEM>>>();
    out_gemm_kernel<<<dim3(DM/128, MTOT/128), 256, GEMM_SMEM>>>(out);
}

// round 10
// speedup vs baseline: 2.7134x; 1.0362x over previous
#include <cuda_runtime.h>
#include <cuda_fp16.h>
#include <math.h>
#include <stdint.h>

#define BB   4
#define TT   2048
#define DM   1024
#define NH   16
#define HD   64
#define MTOT (BB*TT)              // 8192
#define NELEM ((size_t)MTOT*DM)   // 8388608

// ---------------- scratch (device globals: allocation-guard compliant) ------
__device__ __half g_xh[NELEM],  g_xl[NELEM];              // x split [M,K]
__device__ __half g_wqh[(size_t)3*DM*DM], g_wql[(size_t)3*DM*DM];  // Wqkv^T [N,K]
__device__ __half g_woh[(size_t)DM*DM],   g_wol[(size_t)DM*DM];    // Wout^T [N,K]
__device__ __half g_qh[NELEM], g_ql[NELEM];               // rope'd, pre-scaled
__device__ __half g_kh[NELEM], g_kl[NELEM];
__device__ __half g_vh[NELEM], g_vl[NELEM];
__device__ __half g_aoh[NELEM], g_aol[NELEM];             // attn out split [M,K]
__device__ float  g_if[32];                               // rope inv_freq table

__device__ __forceinline__ void split2(float v, __half& h, __half& l) {
    h = __float2half_rn(v);
    l = __float2half_rn(v - __half2float(h));
}

// ---------------- primitives ------------------------------------------------
__device__ __forceinline__ void cp16(void* dst, const void* src) {
    uint32_t d = (uint32_t)__cvta_generic_to_shared(dst);
    asm volatile("cp.async.cg.shared.global [%0], [%1], 16;\n" :: "r"(d), "l"(src));
}
__device__ __forceinline__ void cp_commit() { asm volatile("cp.async.commit_group;\n"); }
template<int N> __device__ __forceinline__ void cp_wait() {
    asm volatile("cp.async.wait_group %0;\n" :: "n"(N));
}
__device__ __forceinline__ void ldsm4(uint32_t* r, const __half* p) {
    uint32_t a = (uint32_t)__cvta_generic_to_shared(p);
    asm volatile("ldmatrix.sync.aligned.m8n8.x4.shared.b16 {%0,%1,%2,%3}, [%4];\n"
        : "=r"(r[0]), "=r"(r[1]), "=r"(r[2]), "=r"(r[3]) : "r"(a));
}
__device__ __forceinline__ void ldsm4t(uint32_t* r, const __half* p) {
    uint32_t a = (uint32_t)__cvta_generic_to_shared(p);
    asm volatile("ldmatrix.sync.aligned.m8n8.x4.trans.shared.b16 {%0,%1,%2,%3}, [%4];\n"
        : "=r"(r[0]), "=r"(r[1]), "=r"(r[2]), "=r"(r[3]) : "r"(a));
}
__device__ __forceinline__ void mma16816(float* c, const uint32_t* a,
                                         uint32_t b0, uint32_t b1) {
    asm volatile("mma.sync.aligned.m16n8k16.row.col.f32.f16.f16.f32 "
        "{%0,%1,%2,%3}, {%4,%5,%6,%7}, {%8,%9}, {%0,%1,%2,%3};\n"
        : "+f"(c[0]), "+f"(c[1]), "+f"(c[2]), "+f"(c[3])
        : "r"(a[0]), "r"(a[1]), "r"(a[2]), "r"(a[3]), "r"(b0), "r"(b1));
}
__device__ __forceinline__ void split_h2(float x, float y, uint32_t& hi, uint32_t& lo) {
    __half hx = __float2half_rn(x), hy = __float2half_rn(y);
    __half lx = __float2half_rn(x - __half2float(hx));
    __half ly = __float2half_rn(y - __half2float(hy));
    __half2 H = __halves2half2(hx, hy), L = __halves2half2(lx, ly);
    hi = *(uint32_t*)&H; lo = *(uint32_t*)&L;
}

extern __shared__ __half gsm[];

// ===========================================================================
// init + splits
// ===========================================================================
__global__ void init_if_kernel()
{
    int d = threadIdx.x;
    if (d < 32) g_if[d] = (float)exp(-(double)d * (log(10000.0) / 32.0));
}

__global__ void split_x_kernel(const float* __restrict__ src)
{
    int i = blockIdx.x * blockDim.x + threadIdx.x;
    if (i >= (int)(NELEM/4)) return;
    float4 v = ((const float4*)src)[i];
    __half hx, lx, hy, ly, hz, lz, hw, lw;
    split2(v.x, hx, lx); split2(v.y, hy, ly);
    split2(v.z, hz, lz); split2(v.w, hw, lw);
    ((__half2*)g_xh)[2*i]   = __halves2half2(hx, hy);
    ((__half2*)g_xh)[2*i+1] = __halves2half2(hz, hw);
    ((__half2*)g_xl)[2*i]   = __halves2half2(lx, ly);
    ((__half2*)g_xl)[2*i+1] = __halves2half2(lz, lw);
}

// transpose + split:  W[K=1024, N] row-major  ->  T[N, K] K-major halves
__global__ void tsplit_kernel(const float* __restrict__ W, int N, int sel)
{
    __shared__ float smt[32][33];
    __half* Th = sel ? g_woh : g_wqh;
    __half* Tl = sel ? g_wol : g_wql;
    const int n0 = blockIdx.x * 32, k0 = blockIdx.y * 32;
    const int tx = threadIdx.x & 31, ty = threadIdx.x >> 5;   // 32 x 8
#pragma unroll
    for (int i = 0; i < 4; i++)
        smt[ty + 8*i][tx] = W[(size_t)(k0 + ty + 8*i) * N + n0 + tx];
    __syncthreads();
#pragma unroll
    for (int i = 0; i < 4; i++) {
        int r = ty + 8*i;
        float v = smt[tx][r];
        __half h, l; split2(v, h, l);
        Th[(size_t)(n0 + r) * DM + k0 + tx] = h;
        Tl[(size_t)(n0 + r) * DM + k0 + tx] = l;
    }
}

// ===========================================================================
// Raw-mma GEMM core: CTA 128x128, warp tile 32x64 (8 warps: 4m x 2n), BK=32,
// split-3, cp.async 2-stage.  A [M,K] row-major halves, B [N,K] K-major halves.
// ===========================================================================
#define ALD 40                     // halfs per smem row (32 + 8)
#define ARR (128*ALD)              // 5120 halfs per array
#define STG_H (4*ARR)              // Ah|Al|Bh|Bl per stage (halfs)
#define GEMM_SMEM (2*STG_H*2)      // 81920 bytes

__device__ __forceinline__ void g_fill(const __half* Ah_g, const __half* Al_g,
                                       const __half* Bh_g, const __half* Bl_g,
                                       int m0, int n0, int k0, int buf)
{
    __half* s = gsm + buf*STG_H;
    const int tid = threadIdx.x;
#pragma unroll
    for (int i = 0; i < 2; i++) {
        int id = tid + i*256;            // 0..511
        int row = id >> 2, u = (id & 3)*8;
        cp16(&s[row*ALD + u],         &Ah_g[(size_t)(m0+row)*DM + k0 + u]);
        cp16(&s[ARR + row*ALD + u],   &Al_g[(size_t)(m0+row)*DM + k0 + u]);
        cp16(&s[2*ARR + row*ALD + u], &Bh_g[(size_t)(n0+row)*DM + k0 + u]);
        cp16(&s[3*ARR + row*ALD + u], &Bl_g[(size_t)(n0+row)*DM + k0 + u]);
    }
    cp_commit();
}

__device__ __forceinline__ void g_compute(int buf, int wm, int wn,
                                          float (*acc)[4], int lane)
{
    __half* Ah = gsm + buf*STG_H;
    __half* Al = Ah + ARR;
    __half* Bh = Ah + 2*ARR;
    __half* Bl = Ah + 3*ARR;
    const int lr   = lane & 15;
    const int lc8  = (lane >> 4) << 3;
    const int krow = ((lane >> 4) << 3) | (lane & 7);
    const int kc8  = ((lane >> 3) & 1) << 3;

#pragma unroll
    for (int kk = 0; kk < 32; kk += 16) {
        uint32_t ah[2][4], al[2][4];
#pragma unroll
        for (int i = 0; i < 2; i++) {
            ldsm4(ah[i], &Ah[(wm*32 + i*16 + lr)*ALD + kk + lc8]);
            ldsm4(al[i], &Al[(wm*32 + i*16 + lr)*ALD + kk + lc8]);
        }
#pragma unroll
        for (int jj = 0; jj < 4; jj++) {
            uint32_t bh[4], bl[4];
            const int boff = (wn*64 + jj*16 + krow)*ALD + kk + kc8;
            ldsm4(bh, &Bh[boff]);
            ldsm4(bl, &Bl[boff]);
#pragma unroll
            for (int i = 0; i < 2; i++) {
                float* c0 = acc[i*8 + 2*jj];
                float* c1 = acc[i*8 + 2*jj + 1];
                mma16816(c0, ah[i], bh[0], bh[1]);
                mma16816(c0, ah[i], bl[0], bl[1]);
                mma16816(c0, al[i], bh[0], bh[1]);
                mma16816(c1, ah[i], bh[2], bh[3]);
                mma16816(c1, ah[i], bl[2], bl[3]);
                mma16816(c1, al[i], bh[2], bh[3]);
            }
        }
    }
}

// acc layout: acc[i*8 + f][x]; i = m-frag (2), f = n8 frag (8), x = 0..3.
// rows: wm*32 + i*16 + (lane>>2) + (x>=2 ? 8 : 0)
// cols: wn*64 + f*8 + (lane&3)*2 + (x&1)
__device__ __forceinline__ void gemm_core(
    const __half* Ah_g, const __half* Al_g,
    const __half* Bh_g, const __half* Bl_g,
    int m0, int n0, float (*acc)[4])
{
    const int lane = threadIdx.x & 31, wid = threadIdx.x >> 5;
    const int wm = wid & 3, wn = wid >> 2;
#pragma unroll
    for (int f = 0; f < 16; f++)
#pragma unroll
        for (int x = 0; x < 4; x++) acc[f][x] = 0.f;

    g_fill(Ah_g, Al_g, Bh_g, Bl_g, m0, n0, 0, 0);
    g_fill(Ah_g, Al_g, Bh_g, Bl_g, m0, n0, 32, 1);
    for (int c = 0; c < 32; c++) {
        if (c + 1 < 32) cp_wait<1>(); else cp_wait<0>();
        __syncthreads();
        g_compute(c & 1, wm, wn, acc, lane);
        __syncthreads();
        if (c + 2 < 32)
            g_fill(Ah_g, Al_g, Bh_g, Bl_g, m0, n0, (c + 2)*32, c & 1);
    }
}

__global__ __launch_bounds__(256) void qkv_gemm_kernel()
{
    const int n0 = blockIdx.x * 128;       // 0..23 -> 3072
    const int m0 = blockIdx.y * 128;
    const int lane = threadIdx.x & 31, wid = threadIdx.x >> 5;
    const int wm = wid & 3, wn = wid >> 2;

    float acc[16][4];
    gemm_core(g_xh, g_xl, g_wqh, g_wql, m0, n0, acc);

    // fused RoPE + split epilogue
    const int col0  = n0 + wn*64;          // head-aligned 64-wide
    const int which = col0 >> 10;          // 0=q,1=k,2=v
    const int h     = (col0 >> 6) & (NH-1);
    __half *Hd, *Ld;
    if (which == 0)      { Hd = g_qh; Ld = g_ql; }
    else if (which == 1) { Hd = g_kh; Ld = g_kl; }
    else                 { Hd = g_vh; Ld = g_vl; }
    const float scale = (which == 0) ? 0.125f : 1.0f;

#pragma unroll
    for (int i = 0; i < 2; i++) {
#pragma unroll
        for (int rr = 0; rr < 2; rr++) {
            const int m = m0 + wm*32 + i*16 + (lane >> 2) + rr*8;
            const int b = m >> 11, t = m & (TT-1);
            const size_t base = (((size_t)(b*NH + h))*TT + t)*HD;
            if (which < 2) {
#pragma unroll
                for (int f = 0; f < 4; f++) {
                    const int d0 = f*8 + (lane & 3)*2;
                    float c0, s0, c1, s1;
                    sincosf((float)t * g_if[d0],     &s0, &c0);
                    sincosf((float)t * g_if[d0 + 1], &s1, &c1);
                    float v1  = acc[i*8 + f][rr*2],     v1b = acc[i*8 + f][rr*2 + 1];
                    float v2  = acc[i*8 + f + 4][rr*2], v2b = acc[i*8 + f + 4][rr*2 + 1];
                    float o1  = (v1*c0 - v2*s0) * scale;
                    float o2  = (v2*c0 + v1*s0) * scale;
                    float o1b = (v1b*c1 - v2b*s1) * scale;
                    float o2b = (v2b*c1 + v1b*s1) * scale;
                    uint32_t h1, l1, h2, l2;
                    split_h2(o1, o1b, h1, l1);
                    split_h2(o2, o2b, h2, l2);
                    *(uint32_t*)&Hd[base + d0]      = h1;
                    *(uint32_t*)&Ld[base + d0]      = l1;
                    *(uint32_t*)&Hd[base + d0 + 32] = h2;
                    *(uint32_t*)&Ld[base + d0 + 32] = l2;
                }
            } else {
#pragma unroll
                for (int f = 0; f < 8; f++) {
                    const int d0 = f*8 + (lane & 3)*2;
                    uint32_t hh, ll;
                    split_h2(acc[i*8 + f][rr*2], acc[i*8 + f][rr*2 + 1], hh, ll);
                    *(uint32_t*)&Hd[base + d0] = hh;
                    *(uint32_t*)&Ld[base + d0] = ll;
                }
            }
        }
    }
}

__global__ __launch_bounds__(256) void out_gemm_kernel(float* __restrict__ Cout)
{
    const int n0 = blockIdx.x * 128;
    const int m0 = blockIdx.y * 128;
    const int lane = threadIdx.x & 31, wid = threadIdx.x >> 5;
    const int wm = wid & 3, wn = wid >> 2;

    float acc[16][4];
    gemm_core(g_aoh, g_aol, g_woh, g_wol, m0, n0, acc);

#pragma unroll
    for (int i = 0; i < 2; i++)
#pragma unroll
        for (int rr = 0; rr < 2; rr++) {
            const int m = m0 + wm*32 + i*16 + (lane >> 2) + rr*8;
            float* dst = Cout + (size_t)m*DM + n0 + wn*64 + (lane & 3)*2;
#pragma unroll
            for (int f = 0; f < 8; f++)
                *(float2*)(dst + f*8) =
                    make_float2(acc[i*8 + f][rr*2], acc[i*8 + f][rr*2 + 1]);
        }
}

// ===========================================================================
// FA2-style flash attention, raw mma.sync, split-3, double-buffered K/V.
// ===========================================================================
#define PLD  72
#define AQ_S (128*PLD)
#define KV_S (64*PLD)
#define KVSTG (4*KV_S)
#define ATTN_SMEM ((2*AQ_S + 2*KVSTG)*2)   // 110592 bytes

__global__ __launch_bounds__(256) void attn_kernel()
{
    __half* Qh = gsm;
    __half* Ql = gsm + AQ_S;

    const int qt   = blockIdx.x;
    const int bh   = blockIdx.y;
    const int tid  = threadIdx.x;
    const int lane = tid & 31;
    const int w    = tid >> 5;
    const int lr   = lane & 15;
    const int lc8  = (lane >> 4) << 3;
    const int krow = ((lane >> 4) << 3) | (lane & 7);
    const int kc8  = ((lane >> 3) & 1) << 3;

    // ---- stage Q tile via cp.async ----
    const size_t qbase = ((size_t)bh*TT + qt*128) * HD;
#pragma unroll
    for (int u = 0; u < 4; u++) {
        int id = tid + u*256;
        int row = id >> 3, kof = (id & 7)*8;
        cp16(&Qh[row*PLD + kof], &g_qh[qbase + (size_t)row*HD + kof]);
        cp16(&Ql[row*PLD + kof], &g_ql[qbase + (size_t)row*HD + kof]);
    }
    cp_commit();
    cp_wait<0>();
    __syncthreads();

    uint32_t qfh[4][4], qfl[4][4];
#pragma unroll
    for (int kk = 0; kk < 4; kk++) {
        ldsm4(qfh[kk], &Qh[(w*16 + lr)*PLD + kk*16 + lc8]);
        ldsm4(qfl[kk], &Ql[(w*16 + lr)*PLD + kk*16 + lc8]);
    }

    float o[8][4];
#pragma unroll
    for (int j = 0; j < 8; j++)
#pragma unroll
        for (int i = 0; i < 4; i++) o[j][i] = 0.f;
    float m0r = -1e30f, m1r = -1e30f, l0r = 0.f, l1r = 0.f;

    const int grow0 = qt*128 + w*16 + (lane >> 2);
    const int ktmax = 2*qt + 1;

    // ---- K/V fill helper (cp.async, one commit per call) ----
    auto fill_kv = [&](int buf, int kt) {
        __half* st = gsm + 2*AQ_S + buf*KVSTG;
        const size_t kvb = ((size_t)bh*TT + kt*64) * HD;
#pragma unroll
        for (int u = 0; u < 2; u++) {
            int id = tid + u*256;
            int row = id >> 3, kof = (id & 7)*8;
            size_t src = kvb + (size_t)row*HD + kof;
            cp16(&st[row*PLD + kof],          &g_kh[src]);
            cp16(&st[KV_S + row*PLD + kof],   &g_kl[src]);
            cp16(&st[2*KV_S + row*PLD + kof], &g_vh[src]);
            cp16(&st[3*KV_S + row*PLD + kof], &g_vl[src]);
        }
        cp_commit();
    };

    fill_kv(0, 0);

    for (int kt = 0; kt <= ktmax; kt++) {
        const int cur = kt & 1;
        if (kt < ktmax) { fill_kv(cur ^ 1, kt + 1); cp_wait<1>(); }
        else            { cp_wait<0>(); }
        __syncthreads();   // stage `cur` data visible to all warps

        if (!(kt*64 > qt*128 + w*16 + 15)) {
            __half* st = gsm + 2*AQ_S + cur*KVSTG;
            __half* Kh = st;
            __half* Kl = st + KV_S;
            __half* Vh = st + 2*KV_S;
            __half* Vl = st + 3*KV_S;

            // ---- S = Q K^T (split-3) ----
            float sc[8][4];
#pragma unroll
            for (int j = 0; j < 8; j++)
#pragma unroll
                for (int i = 0; i < 4; i++) sc[j][i] = 0.f;

#pragma unroll
            for (int kk = 0; kk < 4; kk++) {
#pragma unroll
                for (int jj = 0; jj < 4; jj++) {
                    uint32_t kbh[4], kbl[4];
                    const int koff = (jj*16 + krow)*PLD + kk*16 + kc8;
                    ldsm4(kbh, &Kh[koff]);
                    ldsm4(kbl, &Kl[koff]);
                    mma16816(sc[2*jj],   qfh[kk], kbh[0], kbh[1]);
                    mma16816(sc[2*jj],   qfh[kk], kbl[0], kbl[1]);
                    mma16816(sc[2*jj],   qfl[kk], kbh[0], kbh[1]);
                    mma16816(sc[2*jj+1], qfh[kk], kbh[2], kbh[3]);
                    mma16816(sc[2*jj+1], qfh[kk], kbl[2], kbl[3]);
                    mma16816(sc[2*jj+1], qfl[kk], kbh[2], kbh[3]);
                }
            }

            // ---- causal mask ----
            if (kt*64 + 63 > qt*128 + w*16) {
                const int cb = kt*64 + (lane & 3)*2;
#pragma unroll
                for (int j = 0; j < 8; j++) {
                    int c0 = cb + j*8;
                    if (c0     > grow0)     sc[j][0] = -1e30f;
                    if (c0 + 1 > grow0)     sc[j][1] = -1e30f;
                    if (c0     > grow0 + 8) sc[j][2] = -1e30f;
                    if (c0 + 1 > grow0 + 8) sc[j][3] = -1e30f;
                }
            }

            // ---- online softmax in registers ----
            float mx0 = -1e30f, mx1 = -1e30f;
#pragma unroll
            for (int j = 0; j < 8; j++) {
                mx0 = fmaxf(mx0, fmaxf(sc[j][0], sc[j][1]));
                mx1 = fmaxf(mx1, fmaxf(sc[j][2], sc[j][3]));
            }
            mx0 = fmaxf(mx0, __shfl_xor_sync(0xffffffffu, mx0, 1));
            mx0 = fmaxf(mx0, __shfl_xor_sync(0xffffffffu, mx0, 2));
            mx1 = fmaxf(mx1, __shfl_xor_sync(0xffffffffu, mx1, 1));
            mx1 = fmaxf(mx1, __shfl_xor_sync(0xffffffffu, mx1, 2));

            float mn0 = fmaxf(m0r, mx0), mn1 = fmaxf(m1r, mx1);
            float al0 = __expf(m0r - mn0), al1 = __expf(m1r - mn1);
            m0r = mn0; m1r = mn1;

            float s0 = 0.f, s1 = 0.f;
#pragma unroll
            for (int j = 0; j < 8; j++) {
                sc[j][0] = __expf(sc[j][0] - mn0);  s0 += sc[j][0];
                sc[j][1] = __expf(sc[j][1] - mn0);  s0 += sc[j][1];
                sc[j][2] = __expf(sc[j][2] - mn1);  s1 += sc[j][2];
                sc[j][3] = __expf(sc[j][3] - mn1);  s1 += sc[j][3];
            }
            s0 += __shfl_xor_sync(0xffffffffu, s0, 1);
            s0 += __shfl_xor_sync(0xffffffffu, s0, 2);
            s1 += __shfl_xor_sync(0xffffffffu, s1, 1);
            s1 += __shfl_xor_sync(0xffffffffu, s1, 2);
            l0r = l0r*al0 + s0;
            l1r = l1r*al1 + s1;

#pragma unroll
            for (int j = 0; j < 8; j++) {
                o[j][0] *= al0; o[j][1] *= al0;
                o[j][2] *= al1; o[j][3] *= al1;
            }

            // ---- O += P V (P frags built in registers, split-3) ----
#pragma unroll
            for (int cc = 0; cc < 4; cc++) {
                uint32_t pah[4], pal[4];
                split_h2(sc[2*cc][0],   sc[2*cc][1],   pah[0], pal[0]);
                split_h2(sc[2*cc][2],   sc[2*cc][3],   pah[1], pal[1]);
                split_h2(sc[2*cc+1][0], sc[2*cc+1][1], pah[2], pal[2]);
                split_h2(sc[2*cc+1][2], sc[2*cc+1][3], pah[3], pal[3]);
#pragma unroll
                for (int jj = 0; jj < 4; jj++) {
                    uint32_t vbh[4], vbl[4];
                    const int voff = (cc*16 + lr)*PLD + jj*16 + lc8;
                    ldsm4t(vbh, &Vh[voff]);
                    ldsm4t(vbl, &Vl[voff]);
                    mma16816(o[2*jj],   pah, vbh[0], vbh[1]);
                    mma16816(o[2*jj],   pah, vbl[0], vbl[1]);
                    mma16816(o[2*jj],   pal, vbh[0], vbh[1]);
                    mma16816(o[2*jj+1], pah, vbh[2], vbh[3]);
                    mma16816(o[2*jj+1], pah, vbl[2], vbl[3]);
                    mma16816(o[2*jj+1], pal, vbh[2], vbh[3]);
                }
            }
        }
        __syncthreads();   // all warps done reading stage `cur` before refill
    }

    // ---- epilogue: normalize, split, write [b,t,dm] halves ----
    const float inv0 = 1.f / l0r, inv1 = 1.f / l1r;
    const int b = bh >> 4, h = bh & (NH-1);
    const size_t ob0 = ((size_t)b*TT + grow0)*DM + h*HD;
    const size_t ob1 = ob0 + (size_t)8*DM;
#pragma unroll
    for (int j = 0; j < 8; j++) {
        int col = j*8 + (lane & 3)*2;
        split2(o[j][0]*inv0, g_aoh[ob0+col],   g_aol[ob0+col]);
        split2(o[j][1]*inv0, g_aoh[ob0+col+1], g_aol[ob0+col+1]);
        split2(o[j][2]*inv1, g_aoh[ob1+col],   g_aol[ob1+col]);
        split2(o[j][3]*inv1, g_aoh[ob1+col+1], g_aol[ob1+col+1]);
    }
}

// ===========================================================================
extern "C" void kernel_launch(void* const* d_in, const int* in_sizes, int n_in,
                              void* d_out, int out_size)
{
    const float* x    = (const float*)d_in[0];   // [4,2048,1024]
    const float* Wqkv = (const float*)d_in[1];   // [1024,3072]
    const float* Wout = (const float*)d_in[2];   // [1024,1024]
    float* out = (float*)d_out;                  // [4,2048,1024]

    cudaFuncSetAttribute(qkv_gemm_kernel, cudaFuncAttributeMaxDynamicSharedMemorySize, GEMM_SMEM);
    cudaFuncSetAttribute(out_gemm_kernel, cudaFuncAttributeMaxDynamicSharedMemorySize, GEMM_SMEM);
    cudaFuncSetAttribute(attn_kernel,     cudaFuncAttributeMaxDynamicSharedMemorySize, ATTN_SMEM);

    init_if_kernel<<<1, 32>>>();
    split_x_kernel<<<(NELEM/4 + 255)/256, 256>>>(x);
    tsplit_kernel<<<dim3(3*DM/32, DM/32), 256>>>(Wqkv, 3*DM, 0);
    tsplit_kernel<<<dim3(DM/32,   DM/32), 256>>>(Wout,  DM,   1);

    qkv_gemm_kernel<<<dim3(3*DM/128, MTOT/128), 256, GEMM_SMEM>>>();
    attn_kernel<<<dim3(TT/128, BB*NH), 256, ATTN_SMEM>>>();
    out_gemm_kernel<<<dim3(DM/128, MTOT/128), 256, GEMM_SMEM>>>(out);
}

// round 12
// speedup vs baseline: 3.1374x; 1.1562x over previous
#include <cuda_runtime.h>
#include <cuda_fp16.h>
#include <math.h>
#include <stdint.h>

#define BB   4
#define TT   2048
#define DM   1024
#define NH   16
#define HD   64
#define MTOT (BB*TT)              // 8192
#define NELEM ((size_t)MTOT*DM)   // 8388608

// ---------------- scratch (device globals: allocation-guard compliant) ------
__device__ __half g_xh[NELEM],  g_xl[NELEM];              // x split [M,K]
__device__ __half g_wqh[(size_t)3*DM*DM], g_wql[(size_t)3*DM*DM];  // Wqkv^T [N,K]
__device__ __half g_woh[(size_t)DM*DM],   g_wol[(size_t)DM*DM];    // Wout^T [N,K]
__device__ __half g_qh[NELEM], g_ql[NELEM];               // rope'd, pre-scaled
__device__ __half g_kh[NELEM], g_kl[NELEM];
__device__ __half g_vh[NELEM], g_vl[NELEM];
__device__ __half g_aoh[NELEM], g_aol[NELEM];             // attn out split [M,K]
__device__ float  g_if[32];                               // rope inv_freq table

__device__ __forceinline__ void split2(float v, __half& h, __half& l) {
    h = __float2half_rn(v);
    l = __float2half_rn(v - __half2float(h));
}

// ---------------- primitives ------------------------------------------------
__device__ __forceinline__ void cp16(void* dst, const void* src) {
    uint32_t d = (uint32_t)__cvta_generic_to_shared(dst);
    asm volatile("cp.async.cg.shared.global [%0], [%1], 16;\n" :: "r"(d), "l"(src));
}
__device__ __forceinline__ void cp_commit() { asm volatile("cp.async.commit_group;\n"); }
template<int N> __device__ __forceinline__ void cp_wait() {
    asm volatile("cp.async.wait_group %0;\n" :: "n"(N));
}
__device__ __forceinline__ void ldsm4(uint32_t* r, const __half* p) {
    uint32_t a = (uint32_t)__cvta_generic_to_shared(p);
    asm volatile("ldmatrix.sync.aligned.m8n8.x4.shared.b16 {%0,%1,%2,%3}, [%4];\n"
        : "=r"(r[0]), "=r"(r[1]), "=r"(r[2]), "=r"(r[3]) : "r"(a));
}
__device__ __forceinline__ void ldsm4t(uint32_t* r, const __half* p) {
    uint32_t a = (uint32_t)__cvta_generic_to_shared(p);
    asm volatile("ldmatrix.sync.aligned.m8n8.x4.trans.shared.b16 {%0,%1,%2,%3}, [%4];\n"
        : "=r"(r[0]), "=r"(r[1]), "=r"(r[2]), "=r"(r[3]) : "r"(a));
}
__device__ __forceinline__ void mma16816(float* c, const uint32_t* a,
                                         uint32_t b0, uint32_t b1) {
    asm volatile("mma.sync.aligned.m16n8k16.row.col.f32.f16.f16.f32 "
        "{%0,%1,%2,%3}, {%4,%5,%6,%7}, {%8,%9}, {%0,%1,%2,%3};\n"
        : "+f"(c[0]), "+f"(c[1]), "+f"(c[2]), "+f"(c[3])
        : "r"(a[0]), "r"(a[1]), "r"(a[2]), "r"(a[3]), "r"(b0), "r"(b1));
}
__device__ __forceinline__ void split_h2(float x, float y, uint32_t& hi, uint32_t& lo) {
    __half hx = __float2half_rn(x), hy = __float2half_rn(y);
    __half lx = __float2half_rn(x - __half2float(hx));
    __half ly = __float2half_rn(y - __half2float(hy));
    __half2 H = __halves2half2(hx, hy), L = __halves2half2(lx, ly);
    hi = *(uint32_t*)&H; lo = *(uint32_t*)&L;
}

extern __shared__ __half gsm[];

// ===========================================================================
// init + splits
// ===========================================================================
__global__ void init_if_kernel()
{
    int d = threadIdx.x;
    if (d < 32) g_if[d] = (float)exp(-(double)d * (log(10000.0) / 32.0));
}

__global__ void split_x_kernel(const float* __restrict__ src)
{
    int i = blockIdx.x * blockDim.x + threadIdx.x;
    if (i >= (int)(NELEM/4)) return;
    float4 v = ((const float4*)src)[i];
    __half hx, lx, hy, ly, hz, lz, hw, lw;
    split2(v.x, hx, lx); split2(v.y, hy, ly);
    split2(v.z, hz, lz); split2(v.w, hw, lw);
    ((__half2*)g_xh)[2*i]   = __halves2half2(hx, hy);
    ((__half2*)g_xh)[2*i+1] = __halves2half2(hz, hw);
    ((__half2*)g_xl)[2*i]   = __halves2half2(lx, ly);
    ((__half2*)g_xl)[2*i+1] = __halves2half2(lz, lw);
}

// transpose + split:  W[K=1024, N] row-major  ->  T[N, K] K-major halves
__global__ void tsplit_kernel(const float* __restrict__ W, int N, int sel)
{
    __shared__ float smt[32][33];
    __half* Th = sel ? g_woh : g_wqh;
    __half* Tl = sel ? g_wol : g_wql;
    const int n0 = blockIdx.x * 32, k0 = blockIdx.y * 32;
    const int tx = threadIdx.x & 31, ty = threadIdx.x >> 5;   // 32 x 8
#pragma unroll
    for (int i = 0; i < 4; i++)
        smt[ty + 8*i][tx] = W[(size_t)(k0 + ty + 8*i) * N + n0 + tx];
    __syncthreads();
#pragma unroll
    for (int i = 0; i < 4; i++) {
        int r = ty + 8*i;
        float v = smt[tx][r];
        __half h, l; split2(v, h, l);
        Th[(size_t)(n0 + r) * DM + k0 + tx] = h;
        Tl[(size_t)(n0 + r) * DM + k0 + tx] = l;
    }
}

// ===========================================================================
// Raw-mma GEMM core: CTA 128x128, warp tile 32x64 (8 warps: 4m x 2n), BK=32,
// split-3, cp.async 3-stage pipeline, XOR-swizzled pad-free smem.
// A [M,K] row-major halves, B [N,K] K-major halves.
// Swizzle: row r, 16B-unit u (0..3) -> stored unit u ^ ((r>>1)&3).
// ===========================================================================
#define ARR   4096                 // 128 rows * 32 halfs per array
#define STG_H (4*ARR)              // Ah|Al|Bh|Bl per stage (halfs) = 32 KB
#define GEMM_SMEM (3*STG_H*2)      // 98304 bytes

__device__ __forceinline__ int swz(int row, int u) {
    return row*32 + ((u ^ ((row >> 1) & 3)) << 3);   // in halfs
}

__device__ __forceinline__ void g_fill(const __half* Ah_g, const __half* Al_g,
                                       const __half* Bh_g, const __half* Bl_g,
                                       int m0, int n0, int k0, int buf)
{
    __half* s = gsm + buf*STG_H;
    const int tid = threadIdx.x;
#pragma unroll
    for (int i = 0; i < 2; i++) {
        int id = tid + i*256;            // 0..511
        int row = id >> 2, u = id & 3;
        int off = swz(row, u);
        size_t ga = (size_t)(m0+row)*DM + k0 + u*8;
        size_t gb = (size_t)(n0+row)*DM + k0 + u*8;
        cp16(&s[off],          &Ah_g[ga]);
        cp16(&s[ARR + off],    &Al_g[ga]);
        cp16(&s[2*ARR + off],  &Bh_g[gb]);
        cp16(&s[3*ARR + off],  &Bl_g[gb]);
    }
    cp_commit();
}

__device__ __forceinline__ void g_compute(int buf, int wm, int wn,
                                          float (*acc)[4], int lane)
{
    __half* Ah = gsm + buf*STG_H;
    __half* Al = Ah + ARR;
    __half* Bh = Ah + 2*ARR;
    __half* Bl = Ah + 3*ARR;
    const int lr   = lane & 15;
    const int lc8  = (lane >> 4) << 3;
    const int krow = ((lane >> 4) << 3) | (lane & 7);
    const int kc8  = ((lane >> 3) & 1) << 3;

#pragma unroll
    for (int kk = 0; kk < 32; kk += 16) {
        const int ua = (kk + lc8) >> 3;      // A-operand 16B unit
        const int ub = (kk + kc8) >> 3;      // B-operand 16B unit
        uint32_t ah[2][4], al[2][4];
#pragma unroll
        for (int i = 0; i < 2; i++) {
            const int ar = wm*32 + i*16 + lr;
            ldsm4(ah[i], &Ah[swz(ar, ua)]);
            ldsm4(al[i], &Al[swz(ar, ua)]);
        }
#pragma unroll
        for (int jj = 0; jj < 4; jj++) {
            const int br = wn*64 + jj*16 + krow;
            uint32_t bh[4], bl[4];
            ldsm4(bh, &Bh[swz(br, ub)]);
            ldsm4(bl, &Bl[swz(br, ub)]);
#pragma unroll
            for (int i = 0; i < 2; i++) {
                float* c0 = acc[i*8 + 2*jj];
                float* c1 = acc[i*8 + 2*jj + 1];
                mma16816(c0, ah[i], bh[0], bh[1]);
                mma16816(c0, ah[i], bl[0], bl[1]);
                mma16816(c0, al[i], bh[0], bh[1]);
                mma16816(c1, ah[i], bh[2], bh[3]);
                mma16816(c1, ah[i], bl[2], bl[3]);
                mma16816(c1, al[i], bh[2], bh[3]);
            }
        }
    }
}

// acc layout: acc[i*8 + f][x]; i = m-frag (2), f = n8 frag (8), x = 0..3.
// rows: wm*32 + i*16 + (lane>>2) + (x>=2 ? 8 : 0)
// cols: wn*64 + f*8 + (lane&3)*2 + (x&1)
__device__ __forceinline__ void gemm_core(
    const __half* Ah_g, const __half* Al_g,
    const __half* Bh_g, const __half* Bl_g,
    int m0, int n0, float (*acc)[4])
{
    const int lane = threadIdx.x & 31, wid = threadIdx.x >> 5;
    const int wm = wid & 3, wn = wid >> 2;
#pragma unroll
    for (int f = 0; f < 16; f++)
#pragma unroll
        for (int x = 0; x < 4; x++) acc[f][x] = 0.f;

    g_fill(Ah_g, Al_g, Bh_g, Bl_g, m0, n0, 0, 0);
    g_fill(Ah_g, Al_g, Bh_g, Bl_g, m0, n0, 32, 1);
    for (int c = 0; c < 32; c++) {
        // chunk c ready: for c<31 two groups may be in flight (c, c+1); for
        // the last iteration only chunk 31's group can remain -> full drain.
        if (c < 31) cp_wait<1>(); else cp_wait<0>();
        __syncthreads();
        // slot (c+2)%3 held chunk c-1; all warps finished it before this
        // barrier, so refilling after compute is race-free.
        g_compute(c % 3, wm, wn, acc, lane);
        if (c + 2 < 32)
            g_fill(Ah_g, Al_g, Bh_g, Bl_g, m0, n0, (c + 2)*32, (c + 2) % 3);
    }
}

__global__ __launch_bounds__(256, 2) void qkv_gemm_kernel()
{
    const int n0 = blockIdx.x * 128;       // 0..23 -> 3072
    const int m0 = blockIdx.y * 128;
    const int lane = threadIdx.x & 31, wid = threadIdx.x >> 5;
    const int wm = wid & 3, wn = wid >> 2;

    float acc[16][4];
    gemm_core(g_xh, g_xl, g_wqh, g_wql, m0, n0, acc);

    // fused RoPE + split epilogue
    const int col0  = n0 + wn*64;          // head-aligned 64-wide
    const int which = col0 >> 10;          // 0=q,1=k,2=v
    const int h     = (col0 >> 6) & (NH-1);
    __half *Hd, *Ld;
    if (which == 0)      { Hd = g_qh; Ld = g_ql; }
    else if (which == 1) { Hd = g_kh; Ld = g_kl; }
    else                 { Hd = g_vh; Ld = g_vl; }
    const float scale = (which == 0) ? 0.125f : 1.0f;

#pragma unroll
    for (int i = 0; i < 2; i++) {
#pragma unroll
        for (int rr = 0; rr < 2; rr++) {
            const int m = m0 + wm*32 + i*16 + (lane >> 2) + rr*8;
            const int b = m >> 11, t = m & (TT-1);
            const size_t base = (((size_t)(b*NH + h))*TT + t)*HD;
            if (which < 2) {
#pragma unroll
                for (int f = 0; f < 4; f++) {
                    const int d0 = f*8 + (lane & 3)*2;
                    float c0, s0, c1, s1;
                    sincosf((float)t * g_if[d0],     &s0, &c0);
                    sincosf((float)t * g_if[d0 + 1], &s1, &c1);
                    float v1  = acc[i*8 + f][rr*2],     v1b = acc[i*8 + f][rr*2 + 1];
                    float v2  = acc[i*8 + f + 4][rr*2], v2b = acc[i*8 + f + 4][rr*2 + 1];
                    float o1  = (v1*c0 - v2*s0) * scale;
                    float o2  = (v2*c0 + v1*s0) * scale;
                    float o1b = (v1b*c1 - v2b*s1) * scale;
                    float o2b = (v2b*c1 + v1b*s1) * scale;
                    uint32_t h1, l1, h2, l2;
                    split_h2(o1, o1b, h1, l1);
                    split_h2(o2, o2b, h2, l2);
                    *(uint32_t*)&Hd[base + d0]      = h1;
                    *(uint32_t*)&Ld[base + d0]      = l1;
                    *(uint32_t*)&Hd[base + d0 + 32] = h2;
                    *(uint32_t*)&Ld[base + d0 + 32] = l2;
                }
            } else {
#pragma unroll
                for (int f = 0; f < 8; f++) {
                    const int d0 = f*8 + (lane & 3)*2;
                    uint32_t hh, ll;
                    split_h2(acc[i*8 + f][rr*2], acc[i*8 + f][rr*2 + 1], hh, ll);
                    *(uint32_t*)&Hd[base + d0] = hh;
                    *(uint32_t*)&Ld[base + d0] = ll;
                }
            }
        }
    }
}

__global__ __launch_bounds__(256, 2) void out_gemm_kernel(float* __restrict__ Cout)
{
    const int n0 = blockIdx.x * 128;
    const int m0 = blockIdx.y * 128;
    const int lane = threadIdx.x & 31, wid = threadIdx.x >> 5;
    const int wm = wid & 3, wn = wid >> 2;

    float acc[16][4];
    gemm_core(g_aoh, g_aol, g_woh, g_wol, m0, n0, acc);

#pragma unroll
    for (int i = 0; i < 2; i++)
#pragma unroll
        for (int rr = 0; rr < 2; rr++) {
            const int m = m0 + wm*32 + i*16 + (lane >> 2) + rr*8;
            float* dst = Cout + (size_t)m*DM + n0 + wn*64 + (lane & 3)*2;
#pragma unroll
            for (int f = 0; f < 8; f++)
                *(float2*)(dst + f*8) =
                    make_float2(acc[i*8 + f][rr*2], acc[i*8 + f][rr*2 + 1]);
        }
}

// ===========================================================================
// FA2-style flash attention, raw mma.sync, split-3, double-buffered K/V.
// (unchanged from the round-10 passing kernel)
// ===========================================================================
#define PLD  72
#define AQ_S (128*PLD)
#define KV_S (64*PLD)
#define KVSTG (4*KV_S)
#define ATTN_SMEM ((2*AQ_S + 2*KVSTG)*2)   // 110592 bytes

__global__ __launch_bounds__(256) void attn_kernel()
{
    __half* Qh = gsm;
    __half* Ql = gsm + AQ_S;

    const int qt   = blockIdx.x;
    const int bh   = blockIdx.y;
    const int tid  = threadIdx.x;
    const int lane = tid & 31;
    const int w    = tid >> 5;
    const int lr   = lane & 15;
    const int lc8  = (lane >> 4) << 3;
    const int krow = ((lane >> 4) << 3) | (lane & 7);
    const int kc8  = ((lane >> 3) & 1) << 3;

    // ---- stage Q tile via cp.async ----
    const size_t qbase = ((size_t)bh*TT + qt*128) * HD;
#pragma unroll
    for (int u = 0; u < 4; u++) {
        int id = tid + u*256;
        int row = id >> 3, kof = (id & 7)*8;
        cp16(&Qh[row*PLD + kof], &g_qh[qbase + (size_t)row*HD + kof]);
        cp16(&Ql[row*PLD + kof], &g_ql[qbase + (size_t)row*HD + kof]);
    }
    cp_commit();
    cp_wait<0>();
    __syncthreads();

    uint32_t qfh[4][4], qfl[4][4];
#pragma unroll
    for (int kk = 0; kk < 4; kk++) {
        ldsm4(qfh[kk], &Qh[(w*16 + lr)*PLD + kk*16 + lc8]);
        ldsm4(qfl[kk], &Ql[(w*16 + lr)*PLD + kk*16 + lc8]);
    }

    float o[8][4];
#pragma unroll
    for (int j = 0; j < 8; j++)
#pragma unroll
        for (int i = 0; i < 4; i++) o[j][i] = 0.f;
    float m0r = -1e30f, m1r = -1e30f, l0r = 0.f, l1r = 0.f;

    const int grow0 = qt*128 + w*16 + (lane >> 2);
    const int ktmax = 2*qt + 1;

    // ---- K/V fill helper (cp.async, one commit per call) ----
    auto fill_kv = [&](int buf, int kt) {
        __half* st = gsm + 2*AQ_S + buf*KVSTG;
        const size_t kvb = ((size_t)bh*TT + kt*64) * HD;
#pragma unroll
        for (int u = 0; u < 2; u++) {
            int id = tid + u*256;
            int row = id >> 3, kof = (id & 7)*8;
            size_t src = kvb + (size_t)row*HD + kof;
            cp16(&st[row*PLD + kof],          &g_kh[src]);
            cp16(&st[KV_S + row*PLD + kof],   &g_kl[src]);
            cp16(&st[2*KV_S + row*PLD + kof], &g_vh[src]);
            cp16(&st[3*KV_S + row*PLD + kof], &g_vl[src]);
        }
        cp_commit();
    };

    fill_kv(0, 0);

    for (int kt = 0; kt <= ktmax; kt++) {
        const int cur = kt & 1;
        if (kt < ktmax) { fill_kv(cur ^ 1, kt + 1); cp_wait<1>(); }
        else            { cp_wait<0>(); }
        __syncthreads();   // stage `cur` data visible to all warps

        if (!(kt*64 > qt*128 + w*16 + 15)) {
            __half* st = gsm + 2*AQ_S + cur*KVSTG;
            __half* Kh = st;
            __half* Kl = st + KV_S;
            __half* Vh = st + 2*KV_S;
            __half* Vl = st + 3*KV_S;

            // ---- S = Q K^T (split-3) ----
            float sc[8][4];
#pragma unroll
            for (int j = 0; j < 8; j++)
#pragma unroll
                for (int i = 0; i < 4; i++) sc[j][i] = 0.f;

#pragma unroll
            for (int kk = 0; kk < 4; kk++) {
#pragma unroll
                for (int jj = 0; jj < 4; jj++) {
                    uint32_t kbh[4], kbl[4];
                    const int koff = (jj*16 + krow)*PLD + kk*16 + kc8;
                    ldsm4(kbh, &Kh[koff]);
                    ldsm4(kbl, &Kl[koff]);
                    mma16816(sc[2*jj],   qfh[kk], kbh[0], kbh[1]);
                    mma16816(sc[2*jj],   qfh[kk], kbl[0], kbl[1]);
                    mma16816(sc[2*jj],   qfl[kk], kbh[0], kbh[1]);
                    mma16816(sc[2*jj+1], qfh[kk], kbh[2], kbh[3]);
                    mma16816(sc[2*jj+1], qfh[kk], kbl[2], kbl[3]);
                    mma16816(sc[2*jj+1], qfl[kk], kbh[2], kbh[3]);
                }
            }

            // ---- causal mask ----
            if (kt*64 + 63 > qt*128 + w*16) {
                const int cb = kt*64 + (lane & 3)*2;
#pragma unroll
                for (int j = 0; j < 8; j++) {
                    int c0 = cb + j*8;
                    if (c0     > grow0)     sc[j][0] = -1e30f;
                    if (c0 + 1 > grow0)     sc[j][1] = -1e30f;
                    if (c0     > grow0 + 8) sc[j][2] = -1e30f;
                    if (c0 + 1 > grow0 + 8) sc[j][3] = -1e30f;
                }
            }

            // ---- online softmax in registers ----
            float mx0 = -1e30f, mx1 = -1e30f;
#pragma unroll
            for (int j = 0; j < 8; j++) {
                mx0 = fmaxf(mx0, fmaxf(sc[j][0], sc[j][1]));
                mx1 = fmaxf(mx1, fmaxf(sc[j][2], sc[j][3]));
            }
            mx0 = fmaxf(mx0, __shfl_xor_sync(0xffffffffu, mx0, 1));
            mx0 = fmaxf(mx0, __shfl_xor_sync(0xffffffffu, mx0, 2));
            mx1 = fmaxf(mx1, __shfl_xor_sync(0xffffffffu, mx1, 1));
            mx1 = fmaxf(mx1, __shfl_xor_sync(0xffffffffu, mx1, 2));

            float mn0 = fmaxf(m0r, mx0), mn1 = fmaxf(m1r, mx1);
            float al0 = __expf(m0r - mn0), al1 = __expf(m1r - mn1);
            m0r = mn0; m1r = mn1;

            float s0 = 0.f, s1 = 0.f;
#pragma unroll
            for (int j = 0; j < 8; j++) {
                sc[j][0] = __expf(sc[j][0] - mn0);  s0 += sc[j][0];
                sc[j][1] = __expf(sc[j][1] - mn0);  s0 += sc[j][1];
                sc[j][2] = __expf(sc[j][2] - mn1);  s1 += sc[j][2];
                sc[j][3] = __expf(sc[j][3] - mn1);  s1 += sc[j][3];
            }
            s0 += __shfl_xor_sync(0xffffffffu, s0, 1);
            s0 += __shfl_xor_sync(0xffffffffu, s0, 2);
            s1 += __shfl_xor_sync(0xffffffffu, s1, 1);
            s1 += __shfl_xor_sync(0xffffffffu, s1, 2);
            l0r = l0r*al0 + s0;
            l1r = l1r*al1 + s1;

#pragma unroll
            for (int j = 0; j < 8; j++) {
                o[j][0] *= al0; o[j][1] *= al0;
                o[j][2] *= al1; o[j][3] *= al1;
            }

            // ---- O += P V (P frags built in registers, split-3) ----
#pragma unroll
            for (int cc = 0; cc < 4; cc++) {
                uint32_t pah[4], pal[4];
                split_h2(sc[2*cc][0],   sc[2*cc][1],   pah[0], pal[0]);
                split_h2(sc[2*cc][2],   sc[2*cc][3],   pah[1], pal[1]);
                split_h2(sc[2*cc+1][0], sc[2*cc+1][1], pah[2], pal[2]);
                split_h2(sc[2*cc+1][2], sc[2*cc+1][3], pah[3], pal[3]);
#pragma unroll
                for (int jj = 0; jj < 4; jj++) {
                    uint32_t vbh[4], vbl[4];
                    const int voff = (cc*16 + lr)*PLD + jj*16 + lc8;
                    ldsm4t(vbh, &Vh[voff]);
                    ldsm4t(vbl, &Vl[voff]);
                    mma16816(o[2*jj],   pah, vbh[0], vbh[1]);
                    mma16816(o[2*jj],   pah, vbl[0], vbl[1]);
                    mma16816(o[2*jj],   pal, vbh[0], vbh[1]);
                    mma16816(o[2*jj+1], pah, vbh[2], vbh[3]);
                    mma16816(o[2*jj+1], pah, vbl[2], vbl[3]);
                    mma16816(o[2*jj+1], pal, vbh[2], vbh[3]);
                }
            }
        }
        __syncthreads();   // all warps done reading stage `cur` before refill
    }

    // ---- epilogue: normalize, split, write [b,t,dm] halves ----
    const float inv0 = 1.f / l0r, inv1 = 1.f / l1r;
    const int b = bh >> 4, h = bh & (NH-1);
    const size_t ob0 = ((size_t)b*TT + grow0)*DM + h*HD;
    const size_t ob1 = ob0 + (size_t)8*DM;
#pragma unroll
    for (int j = 0; j < 8; j++) {
        int col = j*8 + (lane & 3)*2;
        split2(o[j][0]*inv0, g_aoh[ob0+col],   g_aol[ob0+col]);
        split2(o[j][1]*inv0, g_aoh[ob0+col+1], g_aol[ob0+col+1]);
        split2(o[j][2]*inv1, g_aoh[ob1+col],   g_aol[ob1+col]);
        split2(o[j][3]*inv1, g_aoh[ob1+col+1], g_aol[ob1+col+1]);
    }
}

// ===========================================================================
extern "C" void kernel_launch(void* const* d_in, const int* in_sizes, int n_in,
                              void* d_out, int out_size)
{
    const float* x    = (const float*)d_in[0];   // [4,2048,1024]
    const float* Wqkv = (const float*)d_in[1];   // [1024,3072]
    const float* Wout = (const float*)d_in[2];   // [1024,1024]
    float* out = (float*)d_out;                  // [4,2048,1024]

    cudaFuncSetAttribute(qkv_gemm_kernel, cudaFuncAttributeMaxDynamicSharedMemorySize, GEMM_SMEM);
    cudaFuncSetAttribute(out_gemm_kernel, cudaFuncAttributeMaxDynamicSharedMemorySize, GEMM_SMEM);
    cudaFuncSetAttribute(attn_kernel,     cudaFuncAttributeMaxDynamicSharedMemorySize, ATTN_SMEM);

    init_if_kernel<<<1, 32>>>();
    split_x_kernel<<<(NELEM/4 + 255)/256, 256>>>(x);
    tsplit_kernel<<<dim3(3*DM/32, DM/32), 256>>>(Wqkv, 3*DM, 0);
    tsplit_kernel<<<dim3(DM/32,   DM/32), 256>>>(Wout,  DM,   1);

    qkv_gemm_kernel<<<dim3(3*DM/128, MTOT/128), 256, GEMM_SMEM>>>();
    attn_kernel<<<dim3(TT/128, BB*NH), 256, ATTN_SMEM>>>();
    out_gemm_kernel<<<dim3(DM/128, MTOT/128), 256, GEMM_SMEM>>>(out);
}